// round 1
// baseline (speedup 1.0000x reference)
#include <cuda_runtime.h>
#include <math.h>

// ---------------- problem constants ----------------
#define NT     26          // number of embedding tables
#define TROWS  100001      // rows per table
#define EDIM   64          // embedding dim
#define BATCH  8192
#define LOOKUPS 4
#define NF     27          // features = 1 dense + 26 embeddings
#define NPAIR  351         // tril(27, -1)
#define RDIM   415         // 64 + 351

#define RB_BOT 32
#define RB_TOP 16
#define FSTR   68          // padded row stride for interaction tile

// ---------------- scratch (allocation-free: device globals) ----------------
__device__ float g_xbot[BATCH * EDIM];           // 2 MB
__device__ float g_R[(size_t)BATCH * RDIM];      // 13.6 MB
__device__ int   g_idx64;                        // 1 if indices are int64

// ---------------- index dtype probe ----------------
// JAX without x64 silently makes the "int64" index tensors int32. Probe the
// raw words: int64 little-endian data has every odd 32-bit word == 0 and the
// even words are valid indices (< 100001). For int32 random indices the odd
// words are themselves random indices (nonzero w.p. 1-1e-5 each), so 32
// consecutive zero odd-words is conclusive.
__global__ void detect_kernel(const int* __restrict__ lsi_raw) {
    if (threadIdx.x == 0 && blockIdx.x == 0) {
        int ok = 1;
        for (int p = 0; p < 32; p++) {
            int lo = lsi_raw[2 * p];
            int hi = lsi_raw[2 * p + 1];
            if (hi != 0 || (unsigned)lo > 100000u) { ok = 0; break; }
        }
        g_idx64 = ok;
    }
}

// ---------------- bottom MLP: 13 -> 512 -> 256 -> 64 (fused) ----------------
// One block handles RB_BOT batch rows. Dynamic smem:
//   h0  : RB_BOT*512 floats
//   buf : RB_BOT*256 floats (holds x tile during layer0, h1 afterwards)
__global__ void __launch_bounds__(256) bottom_kernel(
    const float* __restrict__ x,
    const float* __restrict__ w0, const float* __restrict__ b0,
    const float* __restrict__ w1, const float* __restrict__ b1,
    const float* __restrict__ w2, const float* __restrict__ b2)
{
    extern __shared__ float s[];
    float* h0  = s;                   // RB_BOT*512
    float* buf = s + RB_BOT * 512;    // RB_BOT*256

    const int tid  = threadIdx.x;
    const int row0 = blockIdx.x * RB_BOT;

    // stage x tile (RB_BOT x 13) at head of buf
    for (int i = tid; i < RB_BOT * 13; i += 256)
        buf[i] = x[row0 * 13 + i];
    __syncthreads();

    // layer0: 512 outputs, K=13
    for (int o = tid; o < RB_BOT * 512; o += 256) {
        int r = o >> 9, j = o & 511;
        float acc = b0[j];
        const float* xr = buf + r * 13;
        const float* wr = w0 + j * 13;
#pragma unroll
        for (int k = 0; k < 13; k++) acc += xr[k] * wr[k];
        h0[o] = fmaxf(acc, 0.0f);
    }
    __syncthreads();

    // layer1: 256 outputs, K=512, 4-row register blocking
    {
        const int j = tid;                 // 256 threads == 256 outputs
        const float* wr = w1 + j * 512;
        const float  bj = b1[j];
        for (int r4 = 0; r4 < RB_BOT; r4 += 4) {
            float a0 = bj, a1 = bj, a2 = bj, a3 = bj;
            const float* h = h0 + r4 * 512;
#pragma unroll 8
            for (int k = 0; k < 512; k++) {
                float w = wr[k];
                a0 += h[k]          * w;
                a1 += h[512 + k]    * w;
                a2 += h[1024 + k]   * w;
                a3 += h[1536 + k]   * w;
            }
            buf[(r4 + 0) * 256 + j] = fmaxf(a0, 0.0f);
            buf[(r4 + 1) * 256 + j] = fmaxf(a1, 0.0f);
            buf[(r4 + 2) * 256 + j] = fmaxf(a2, 0.0f);
            buf[(r4 + 3) * 256 + j] = fmaxf(a3, 0.0f);
        }
    }
    __syncthreads();

    // layer2: 64 outputs, K=256
    for (int o = tid; o < RB_BOT * 64; o += 256) {
        int r = o >> 6, j = o & 63;
        float acc = b2[j];
        const float* h  = buf + r * 256;
        const float* wr = w2 + j * 256;
#pragma unroll 8
        for (int k = 0; k < 256; k++) acc += h[k] * wr[k];
        g_xbot[(row0 + r) * 64 + j] = fmaxf(acc, 0.0f);
    }
}

// ---------------- embedding gather + mean-pool + interaction ----------------
// One block per batch row. Builds F (27 x 64, padded stride) in smem,
// computes Z = F F^T lower triangle, writes R row = [x_bot | Zflat].
__global__ void __launch_bounds__(256) embed_kernel(
    const void*  __restrict__ lsi_raw,
    const float* __restrict__ emb)
{
    __shared__ float F[NF * FSTR];
    __shared__ int   sidx[NT * LOOKUPS];

    const int b   = blockIdx.x;
    const int tid = threadIdx.x;
    const int is64 = g_idx64;

    // stage the 104 indices for this batch row
    if (tid < NT * LOOKUPS) {
        int t = tid >> 2, l = tid & 3;
        long long off = (long long)t * (BATCH * LOOKUPS) + (long long)b * LOOKUPS + l;
        int idx = is64 ? (int)((const long long*)lsi_raw)[off]
                       : ((const int*)lsi_raw)[off];
        sidx[tid] = idx;
    }
    if (tid < EDIM)
        F[tid] = g_xbot[b * EDIM + tid];     // feature row 0 = bottom-MLP out
    __syncthreads();

    // gather + mean over 4 lookups; consecutive threads -> consecutive d (coalesced)
    for (int q = tid; q < NT * EDIM; q += 256) {
        int t = q >> 6, d = q & 63;
        const float* base = emb + (size_t)t * TROWS * EDIM;
        float acc = 0.0f;
#pragma unroll
        for (int l = 0; l < LOOKUPS; l++)
            acc += base[(size_t)sidx[t * 4 + l] * EDIM + d];
        F[(t + 1) * FSTR + d] = acc * 0.25f;
    }
    __syncthreads();

    float* Rrow = g_R + (size_t)b * RDIM;
    if (tid < EDIM) Rrow[tid] = F[tid];

    // lower-triangle dot products in np.tril_indices order:
    // p in row i occupies [i(i-1)/2, i(i+1)/2)
    for (int p = tid; p < NPAIR; p += 256) {
        int i = (int)((1.0f + sqrtf(1.0f + 8.0f * (float)p)) * 0.5f);
        while (i * (i - 1) / 2 > p) i--;
        while ((i + 1) * i / 2 <= p) i++;
        int j = p - i * (i - 1) / 2;
        const float* Fi = F + i * FSTR;
        const float* Fj = F + j * FSTR;
        float acc = 0.0f;
#pragma unroll 16
        for (int k = 0; k < EDIM; k++) acc += Fi[k] * Fj[k];
        Rrow[64 + p] = acc;
    }
}

// ---------------- top MLP: 415 -> 512 -> 256 -> 1 (fused) ----------------
// One block handles RB_TOP rows. Dynamic smem:
//   Rs : RB_TOP*416 floats (input tile; reused as h1 after layer0)
//   h0 : RB_TOP*512 floats
__global__ void __launch_bounds__(256) top_kernel(
    const float* __restrict__ w0, const float* __restrict__ b0,
    const float* __restrict__ w1, const float* __restrict__ b1,
    const float* __restrict__ w2, const float* __restrict__ b2,
    float* __restrict__ out)
{
    extern __shared__ float s[];
    float* Rs = s;                    // RB_TOP*416
    float* h0 = s + RB_TOP * 416;     // RB_TOP*512

    const int tid  = threadIdx.x;
    const int row0 = blockIdx.x * RB_TOP;

    for (int i = tid; i < RB_TOP * RDIM; i += 256) {
        int r = i / RDIM, k = i % RDIM;
        Rs[r * 416 + k] = g_R[(size_t)(row0 + r) * RDIM + k];
    }
    __syncthreads();

    // layer0: 512 outputs, K=415, 4-row blocking
    for (int jj = 0; jj < 2; jj++) {
        const int j = tid + jj * 256;
        const float* wr = w0 + (size_t)j * RDIM;
        const float  bj = b0[j];
        for (int r4 = 0; r4 < RB_TOP; r4 += 4) {
            float a0 = bj, a1 = bj, a2 = bj, a3 = bj;
            const float* h = Rs + r4 * 416;
#pragma unroll 5
            for (int k = 0; k < RDIM; k++) {
                float w = wr[k];
                a0 += h[k]          * w;
                a1 += h[416 + k]    * w;
                a2 += h[832 + k]    * w;
                a3 += h[1248 + k]   * w;
            }
            h0[(r4 + 0) * 512 + j] = fmaxf(a0, 0.0f);
            h0[(r4 + 1) * 512 + j] = fmaxf(a1, 0.0f);
            h0[(r4 + 2) * 512 + j] = fmaxf(a2, 0.0f);
            h0[(r4 + 3) * 512 + j] = fmaxf(a3, 0.0f);
        }
    }
    __syncthreads();

    // layer1: 256 outputs, K=512; h1 overlays Rs (dead after layer0)
    float* h1 = Rs;
    {
        const int j = tid;
        const float* wr = w1 + j * 512;
        const float  bj = b1[j];
        for (int r4 = 0; r4 < RB_TOP; r4 += 4) {
            float a0 = bj, a1 = bj, a2 = bj, a3 = bj;
            const float* h = h0 + r4 * 512;
#pragma unroll 8
            for (int k = 0; k < 512; k++) {
                float w = wr[k];
                a0 += h[k]          * w;
                a1 += h[512 + k]    * w;
                a2 += h[1024 + k]   * w;
                a3 += h[1536 + k]   * w;
            }
            h1[(r4 + 0) * 256 + j] = fmaxf(a0, 0.0f);
            h1[(r4 + 1) * 256 + j] = fmaxf(a1, 0.0f);
            h1[(r4 + 2) * 256 + j] = fmaxf(a2, 0.0f);
            h1[(r4 + 3) * 256 + j] = fmaxf(a3, 0.0f);
        }
    }
    __syncthreads();

    // layer2: 1 output per row, K=256. 16 threads per row + shfl reduce.
    {
        const int r   = tid >> 4;
        const int l16 = tid & 15;
        const float* h = h1 + r * 256;
        float acc = 0.0f;
#pragma unroll 4
        for (int k = l16; k < 256; k += 16) acc += h[k] * w2[k];
#pragma unroll
        for (int ofs = 8; ofs > 0; ofs >>= 1)
            acc += __shfl_down_sync(0xffffffffu, acc, ofs, 16);
        if (l16 == 0) out[row0 + r] = acc + b2[0];
    }
}

// ---------------- launch ----------------
extern "C" void kernel_launch(void* const* d_in, const int* in_sizes, int n_in,
                              void* d_out, int out_size)
{
    const float* dense_x = (const float*)d_in[0];
    // d_in[1] = lS_o (unused: reference reshapes lS_i directly)
    const void*  lsi     = d_in[2];
    const float* emb     = (const float*)d_in[3];
    const float* bw0 = (const float*)d_in[4];
    const float* bb0 = (const float*)d_in[5];
    const float* bw1 = (const float*)d_in[6];
    const float* bb1 = (const float*)d_in[7];
    const float* bw2 = (const float*)d_in[8];
    const float* bb2 = (const float*)d_in[9];
    const float* tw0 = (const float*)d_in[10];
    const float* tb0 = (const float*)d_in[11];
    const float* tw1 = (const float*)d_in[12];
    const float* tb1 = (const float*)d_in[13];
    const float* tw2 = (const float*)d_in[14];
    const float* tb2 = (const float*)d_in[15];
    float* out = (float*)d_out;

    const int bot_smem = (RB_BOT * 512 + RB_BOT * 256) * 4;   // 98304
    const int top_smem = (RB_TOP * 416 + RB_TOP * 512) * 4;   // 59392
    cudaFuncSetAttribute(bottom_kernel, cudaFuncAttributeMaxDynamicSharedMemorySize, bot_smem);
    cudaFuncSetAttribute(top_kernel,    cudaFuncAttributeMaxDynamicSharedMemorySize, top_smem);

    detect_kernel<<<1, 32>>>((const int*)lsi);
    bottom_kernel<<<BATCH / RB_BOT, 256, bot_smem>>>(dense_x, bw0, bb0, bw1, bb1, bw2, bb2);
    embed_kernel<<<BATCH, 256>>>(lsi, emb);
    top_kernel<<<BATCH / RB_TOP, 256, top_smem>>>(tw0, tb0, tw1, tb1, tw2, tb2, out);
}

// round 3
// speedup vs baseline: 10.3257x; 10.3257x over previous
#include <cuda_runtime.h>
#include <math.h>

// ---------------- problem constants ----------------
#define NT      26
#define TROWS   100001
#define EDIM    64
#define BATCH   8192
#define LOOKUPS 4
#define NF      27
#define NPAIR   351
#define RDIM    415
#define RSTR    416          // padded R row stride (float4-aligned)
#define FSTR    68

// ---------------- scratch (allocation-free device globals) ----------------
__device__ float g_buf512[(size_t)BATCH * 512];   // h0 (bottom), then t0 (top)
__device__ float g_buf256[(size_t)BATCH * 256];   // h1 (bottom), then t1 (top)
__device__ float g_xbot[(size_t)BATCH * EDIM];
__device__ float g_R[(size_t)BATCH * RSTR];
__device__ float g_w0p[512 * RSTR];               // top w0 padded to K=416
__device__ int   g_idx64;

// ---------------- index dtype probe ----------------
__global__ void detect_kernel(const int* __restrict__ lsi_raw) {
    if (threadIdx.x == 0 && blockIdx.x == 0) {
        int ok = 1;
        for (int p = 0; p < 32; p++) {
            int lo = lsi_raw[2 * p];
            int hi = lsi_raw[2 * p + 1];
            if (hi != 0 || (unsigned)lo > 100000u) { ok = 0; break; }
        }
        g_idx64 = ok;
    }
}

// ---------------- pad top w0: [512][415] -> [512][416] (col 415 = 0) -------
__global__ void pad_w0_kernel(const float* __restrict__ w0) {
    int i = blockIdx.x * 256 + threadIdx.x;
    if (i < 512 * RSTR) {
        int r = i / RSTR, c = i % RSTR;
        g_w0p[i] = (c < RDIM) ? w0[r * RDIM + c] : 0.0f;
    }
}

// ---------------- bottom layer0: 13 -> 512 (weights fully in smem) --------
#define B0_ROWS 32
__global__ void __launch_bounds__(256) bot0_kernel(
    const float* __restrict__ x,
    const float* __restrict__ w, const float* __restrict__ b)
{
    __shared__ float ws[512 * 13];
    __shared__ float bs[512];
    __shared__ float xs[B0_ROWS * 13];
    const int tid  = threadIdx.x;
    const int row0 = blockIdx.x * B0_ROWS;

    for (int i = tid; i < 512 * 13; i += 256) ws[i] = w[i];
    for (int i = tid; i < 512; i += 256)      bs[i] = b[i];
    for (int i = tid; i < B0_ROWS * 13; i += 256) xs[i] = x[row0 * 13 + i];
    __syncthreads();

    for (int o = tid; o < B0_ROWS * 512; o += 256) {
        int r = o >> 9, j = o & 511;
        float acc = bs[j];
        const float* xr = xs + r * 13;
        const float* wr = ws + j * 13;
#pragma unroll
        for (int k = 0; k < 13; k++) acc += xr[k] * wr[k];
        g_buf512[(size_t)(row0 + r) * 512 + j] = fmaxf(acc, 0.0f);
    }
}

// ---------------- tiled GEMM: C = [relu](A * W^T + bias) -------------------
// A:[M,K] row-major (lda), W:[N,K] row-major (ldw). BM=BN=64, BK=32.
// 256 threads, 4x4 micro-tile, rows/cols strided by 16 (bank-friendly).
// lda/ldw/K must be multiples of 4 (K a multiple of 32); all callers comply.
#define BM  64
#define BN  64
#define BK  32
#define BKP 36

__global__ void __launch_bounds__(256) gemm_kernel(
    const float* __restrict__ A, int lda,
    const float* __restrict__ W, int ldw,
    const float* __restrict__ bias,
    float* __restrict__ C, int ldc,
    int K, int relu)
{
    __shared__ float As[BM * BKP];
    __shared__ float Ws[BN * BKP];
    const int tid  = threadIdx.x;
    const size_t row0 = (size_t)blockIdx.x * BM;
    const size_t col0 = (size_t)blockIdx.y * BN;
    const int lr = tid >> 3;          // 0..31 load row
    const int lk = (tid & 7) << 2;    // 0..28 load k offset (float4)
    const int tn = tid & 15;
    const int tm = tid >> 4;

    const float* Ag = A + (row0 + lr) * lda + lk;
    const float* Wg = W + (col0 + lr) * ldw + lk;

    float acc[4][4];
#pragma unroll
    for (int j = 0; j < 4; j++) {
        float bj = bias[col0 + tn + 16 * j];
#pragma unroll
        for (int i = 0; i < 4; i++) acc[i][j] = bj;
    }

    float4 pa0 = *(const float4*)(Ag);
    float4 pa1 = *(const float4*)(Ag + (size_t)32 * lda);
    float4 pw0 = *(const float4*)(Wg);
    float4 pw1 = *(const float4*)(Wg + (size_t)32 * ldw);

    const int ntiles = K / BK;
    for (int t = 0; t < ntiles; t++) {
        __syncthreads();
        *(float4*)(As + lr * BKP + lk)        = pa0;
        *(float4*)(As + (lr + 32) * BKP + lk) = pa1;
        *(float4*)(Ws + lr * BKP + lk)        = pw0;
        *(float4*)(Ws + (lr + 32) * BKP + lk) = pw1;
        __syncthreads();

        if (t + 1 < ntiles) {          // prefetch next tile (hides L2 latency)
            const float* Ag2 = Ag + (t + 1) * BK;
            const float* Wg2 = Wg + (t + 1) * BK;
            pa0 = *(const float4*)(Ag2);
            pa1 = *(const float4*)(Ag2 + (size_t)32 * lda);
            pw0 = *(const float4*)(Wg2);
            pw1 = *(const float4*)(Wg2 + (size_t)32 * ldw);
        }

#pragma unroll
        for (int kk = 0; kk < BK; kk += 4) {
            float4 av[4], wv[4];
#pragma unroll
            for (int i = 0; i < 4; i++)
                av[i] = *(const float4*)(As + (tm + 16 * i) * BKP + kk);
#pragma unroll
            for (int j = 0; j < 4; j++)
                wv[j] = *(const float4*)(Ws + (tn + 16 * j) * BKP + kk);
#pragma unroll
            for (int i = 0; i < 4; i++)
#pragma unroll
                for (int j = 0; j < 4; j++) {
                    acc[i][j] += av[i].x * wv[j].x;
                    acc[i][j] += av[i].y * wv[j].y;
                    acc[i][j] += av[i].z * wv[j].z;
                    acc[i][j] += av[i].w * wv[j].w;
                }
        }
    }

#pragma unroll
    for (int i = 0; i < 4; i++)
#pragma unroll
        for (int j = 0; j < 4; j++) {
            float v = acc[i][j];
            if (relu) v = fmaxf(v, 0.0f);
            C[(row0 + tm + 16 * i) * (size_t)ldc + col0 + tn + 16 * j] = v;
        }
}

// ---------------- embedding gather + mean-pool + interaction --------------
__global__ void __launch_bounds__(256) embed_kernel(
    const void*  __restrict__ lsi_raw,
    const float* __restrict__ emb)
{
    __shared__ float F[NF * FSTR];
    __shared__ int   sidx[NT * LOOKUPS];

    const int b    = blockIdx.x;
    const int tid  = threadIdx.x;
    const int is64 = g_idx64;

    if (tid < NT * LOOKUPS) {
        int t = tid >> 2, l = tid & 3;
        long long off = (long long)t * (BATCH * LOOKUPS) + (long long)b * LOOKUPS + l;
        int idx = is64 ? (int)((const long long*)lsi_raw)[off]
                       : ((const int*)lsi_raw)[off];
        sidx[tid] = idx;
    }
    if (tid < EDIM)
        F[tid] = g_xbot[(size_t)b * EDIM + tid];
    __syncthreads();

    for (int q = tid; q < NT * EDIM; q += 256) {
        int t = q >> 6, d = q & 63;
        const float* base = emb + (size_t)t * TROWS * EDIM;
        float acc = 0.0f;
#pragma unroll
        for (int l = 0; l < LOOKUPS; l++)
            acc += base[(size_t)sidx[t * 4 + l] * EDIM + d];
        F[(t + 1) * FSTR + d] = acc * 0.25f;
    }
    __syncthreads();

    float* Rrow = g_R + (size_t)b * RSTR;
    if (tid < EDIM) Rrow[tid] = F[tid];
    if (tid == 0)   Rrow[RDIM] = 0.0f;           // K padding column

    for (int p = tid; p < NPAIR; p += 256) {
        int i = (int)((1.0f + sqrtf(1.0f + 8.0f * (float)p)) * 0.5f);
        while (i * (i - 1) / 2 > p) i--;
        while ((i + 1) * i / 2 <= p) i++;
        int j = p - i * (i - 1) / 2;
        const float* Fi = F + i * FSTR;
        const float* Fj = F + j * FSTR;
        float acc = 0.0f;
#pragma unroll 16
        for (int k = 0; k < EDIM; k++) acc += Fi[k] * Fj[k];
        Rrow[64 + p] = acc;
    }
}

// ---------------- top layer2: 256 -> 1 (warp per row) ---------------------
__global__ void __launch_bounds__(256) top2_kernel(
    const float* __restrict__ A,
    const float* __restrict__ w, const float* __restrict__ b,
    float* __restrict__ out)
{
    const int warp = threadIdx.x >> 5, lane = threadIdx.x & 31;
    const int row  = blockIdx.x * 8 + warp;
    const float* a = A + (size_t)row * 256;
    float4 a0 = *(const float4*)(a + lane * 4);
    float4 a1 = *(const float4*)(a + 128 + lane * 4);
    float4 w0 = *(const float4*)(w + lane * 4);
    float4 w1 = *(const float4*)(w + 128 + lane * 4);
    float acc = a0.x * w0.x + a0.y * w0.y + a0.z * w0.z + a0.w * w0.w
              + a1.x * w1.x + a1.y * w1.y + a1.z * w1.z + a1.w * w1.w;
#pragma unroll
    for (int o = 16; o; o >>= 1) acc += __shfl_down_sync(0xffffffffu, acc, o);
    if (lane == 0) out[row] = acc + b[0];
}

// ---------------- launch ----------------
extern "C" void kernel_launch(void* const* d_in, const int* in_sizes, int n_in,
                              void* d_out, int out_size)
{
    const float* dense_x = (const float*)d_in[0];
    const void*  lsi     = d_in[2];
    const float* emb     = (const float*)d_in[3];
    const float* bw0 = (const float*)d_in[4];
    const float* bb0 = (const float*)d_in[5];
    const float* bw1 = (const float*)d_in[6];
    const float* bb1 = (const float*)d_in[7];
    const float* bw2 = (const float*)d_in[8];
    const float* bb2 = (const float*)d_in[9];
    const float* tw0 = (const float*)d_in[10];
    const float* tb0 = (const float*)d_in[11];
    const float* tw1 = (const float*)d_in[12];
    const float* tb1 = (const float*)d_in[13];
    const float* tw2 = (const float*)d_in[14];
    const float* tb2 = (const float*)d_in[15];
    float* out = (float*)d_out;

    float *buf512, *buf256, *xbot, *R, *w0p;
    cudaGetSymbolAddress((void**)&buf512, g_buf512);
    cudaGetSymbolAddress((void**)&buf256, g_buf256);
    cudaGetSymbolAddress((void**)&xbot,   g_xbot);
    cudaGetSymbolAddress((void**)&R,      g_R);
    cudaGetSymbolAddress((void**)&w0p,    g_w0p);

    detect_kernel<<<1, 32>>>((const int*)lsi);
    pad_w0_kernel<<<(512 * RSTR + 255) / 256, 256>>>(tw0);

    // bottom MLP
    bot0_kernel<<<BATCH / B0_ROWS, 256>>>(dense_x, bw0, bb0);
    gemm_kernel<<<dim3(BATCH / BM, 256 / BN), 256>>>(buf512, 512, bw1, 512, bb1,
                                                     buf256, 256, 512, 1);
    gemm_kernel<<<dim3(BATCH / BM, 64 / BN), 256>>>(buf256, 256, bw2, 256, bb2,
                                                    xbot, 64, 256, 1);
    // embeddings + interaction -> R
    embed_kernel<<<BATCH, 256>>>(lsi, emb);

    // top MLP
    gemm_kernel<<<dim3(BATCH / BM, 512 / BN), 256>>>(R, RSTR, w0p, RSTR, tb0,
                                                     buf512, 512, RSTR, 1);
    gemm_kernel<<<dim3(BATCH / BM, 256 / BN), 256>>>(buf512, 512, tw1, 512, tb1,
                                                     buf256, 256, 512, 1);
    top2_kernel<<<BATCH / 8, 256>>>(buf256, tw2, tb2, out);
}

// round 6
// speedup vs baseline: 12.4297x; 1.2038x over previous
#include <cuda_runtime.h>
#include <cuda_bf16.h>
#include <math.h>
#include <stdint.h>

// ---------------- problem constants ----------------
#define NT      26
#define TROWS   100001
#define EDIM    64
#define BATCH   8192
#define LOOKUPS 4
#define NF      27
#define NPAIR   351
#define RDIM    415
#define RKP     448           // top-L0 K padded to multiple of 64
#define FSTR    68

// ---------------- scratch (allocation-free device globals) ----------------
// bf16 activation triples: row = [hi | lo | hi], stride 3*Kp
__device__ __align__(16) __nv_bfloat16 g_h0t[(size_t)BATCH * 1536];  // Kp=512
__device__ __align__(16) __nv_bfloat16 g_a1t[(size_t)BATCH * 768];   // Kp=256
__device__ __align__(16) __nv_bfloat16 g_Rt [(size_t)BATCH * 1344];  // Kp=448
__device__ __align__(16) __nv_bfloat16 g_t0t[(size_t)BATCH * 1536];  // Kp=512
__device__ __align__(16) float g_xbot[(size_t)BATCH * EDIM];
__device__ __align__(16) float g_t1[(size_t)BATCH * 256];
// bf16 weight triples: row = [hi | hi | lo]
__device__ __align__(16) __nv_bfloat16 g_wb1t[256 * 1536];
__device__ __align__(16) __nv_bfloat16 g_wb2t[64  * 768];
__device__ __align__(16) __nv_bfloat16 g_wt0t[512 * 1344];
__device__ __align__(16) __nv_bfloat16 g_wt1t[256 * 1536];
__device__ int g_idx64;

// ---------------- helpers ----------------
__device__ __forceinline__ uint32_t smem_u32(const void* p) {
    uint32_t a;
    asm("{ .reg .u64 t; cvta.to.shared.u64 t, %1; cvt.u32.u64 %0, t; }" : "=r"(a) : "l"(p));
    return a;
}
__device__ __forceinline__ uint32_t sw128(uint32_t o) { return o ^ ((o >> 3) & 0x70); }

#define LDSM_X4(r0, r1, r2, r3, a) \
    asm volatile("ldmatrix.sync.aligned.m8n8.x4.shared.b16 {%0,%1,%2,%3}, [%4];" \
                 : "=r"(r0), "=r"(r1), "=r"(r2), "=r"(r3) : "r"(a))

#define MMA16816(c, a0, a1, a2, a3, b0, b1) \
    asm volatile("mma.sync.aligned.m16n8k16.row.col.f32.bf16.bf16.f32 " \
                 "{%0,%1,%2,%3},{%4,%5,%6,%7},{%8,%9},{%0,%1,%2,%3};" \
                 : "+f"((c)[0]), "+f"((c)[1]), "+f"((c)[2]), "+f"((c)[3]) \
                 : "r"(a0), "r"(a1), "r"(a2), "r"(a3), "r"(b0), "r"(b1))

// activation triple: [hi | lo | hi]
__device__ __forceinline__ void write3a(__nv_bfloat16* row, int Kp, int j, float v) {
    __nv_bfloat16 hi = __float2bfloat16(v);
    __nv_bfloat16 lo = __float2bfloat16(v - __bfloat162float(hi));
    row[j] = hi; row[Kp + j] = lo; row[2 * Kp + j] = hi;
}
// weight triple: [hi | hi | lo]   (so A·W over 3K = hi·hi + lo·hi + hi·lo)
__device__ __forceinline__ void write3w(__nv_bfloat16* row, int Kp, int j, float v) {
    __nv_bfloat16 hi = __float2bfloat16(v);
    __nv_bfloat16 lo = __float2bfloat16(v - __bfloat162float(hi));
    row[j] = hi; row[Kp + j] = hi; row[2 * Kp + j] = lo;
}

// ---------------- index dtype probe ----------------
__global__ void detect_kernel(const int* __restrict__ lsi_raw) {
    if (threadIdx.x == 0 && blockIdx.x == 0) {
        int ok = 1;
        for (int p = 0; p < 32; p++) {
            int lo = lsi_raw[2 * p], hi = lsi_raw[2 * p + 1];
            if (hi != 0 || (unsigned)lo > 100000u) { ok = 0; break; }
        }
        g_idx64 = ok;
    }
}

// ---------------- weight convert: fp32 [N][K] -> bf16 triple [N][3*Kp] -----
__global__ void wconv_kernel(const float* __restrict__ w, int K, int Kp, int N,
                             __nv_bfloat16* __restrict__ w3) {
    int i = blockIdx.x * 256 + threadIdx.x;
    if (i >= N * Kp) return;
    int n = i / Kp, k = i % Kp;
    float v = (k < K) ? w[n * K + k] : 0.0f;
    write3w(w3 + (size_t)n * 3 * Kp, Kp, k, v);
}

// ---------------- bottom layer0: 13 -> 512, triple out ---------------------
#define B0_ROWS 32
__global__ void __launch_bounds__(256) bot0_kernel(
    const float* __restrict__ x,
    const float* __restrict__ w, const float* __restrict__ b)
{
    __shared__ float ws[512 * 13];
    __shared__ float bs[512];
    __shared__ float xs[B0_ROWS * 13];
    const int tid  = threadIdx.x;
    const int row0 = blockIdx.x * B0_ROWS;

    for (int i = tid; i < 512 * 13; i += 256) ws[i] = w[i];
    for (int i = tid; i < 512; i += 256)      bs[i] = b[i];
    for (int i = tid; i < B0_ROWS * 13; i += 256) xs[i] = x[row0 * 13 + i];
    __syncthreads();

    for (int o = tid; o < B0_ROWS * 512; o += 256) {
        int r = o >> 9, j = o & 511;
        float acc = bs[j];
        const float* xr = xs + r * 13;
        const float* wr = ws + j * 13;
#pragma unroll
        for (int k = 0; k < 13; k++) acc += xr[k] * wr[k];
        write3a(g_h0t + (size_t)(row0 + r) * 1536, 512, j, fmaxf(acc, 0.0f));
    }
}

// ---------------- mma.sync bf16 GEMM: C = relu(A*W^T + bias) ---------------
// A3:[M][K3], W3:[N][K3] bf16. BM=128, BN=64, BK=64. 256 threads, 8 warps
// in 4(M)x2(N); warp tile 32x32 = 2x4 m16n8k16 fragments.
// mode 0: fp32 out Cf[ldc]; mode 1: bf16 activation-triple out C3 (Kp=KpOut).
#define GBN 64
__global__ void __launch_bounds__(256) gemm_mma(
    const __nv_bfloat16* __restrict__ A3,
    const __nv_bfloat16* __restrict__ W3,
    const float* __restrict__ bias, int K3,
    float* __restrict__ Cf, int ldc,
    __nv_bfloat16* __restrict__ C3, int KpOut, int mode)
{
    extern __shared__ char dynsm[];
    const int tid  = threadIdx.x;
    const int wid  = tid >> 5;
    const int lane = tid & 31;
    const int warp_m = wid >> 1;        // 0..3
    const int warp_n = wid & 1;         // 0..1
    const size_t row0 = (size_t)blockIdx.x * 128;
    const size_t col0 = (size_t)blockIdx.y * GBN;

    // 1024-aligned tile area: [A0 16K][A1 16K][B0 8K][B1 8K]
    uint32_t dbase = smem_u32(dynsm);
    uint32_t abase = (dbase + 1023) & ~1023u;
    char* sb = dynsm + (abase - dbase);
    char* sA[2] = { sb, sb + 16384 };
    char* sB[2] = { sb + 32768, sb + 40960 };
    const uint32_t uA[2] = { abase, abase + 16384 };
    const uint32_t uB[2] = { abase + 32768, abase + 40960 };
    float* sepi = (float*)sb;

    // global load mapping: 128B rows, 16B per thread
    const int lrow = tid >> 3;          // 0..31
    const int lcol = tid & 7;           // 16B units
    const __nv_bfloat16* Abase = A3 + (row0 + lrow) * (size_t)K3 + lcol * 8;
    const __nv_bfloat16* Wbase = W3 + (col0 + lrow) * (size_t)K3 + lcol * 8;

    // ldmatrix per-lane byte offsets (row part + k-seg part), swizzled per use
    const int aoff0 = (warp_m * 32 + 0  + (lane & 15)) * 128 + (lane >> 4) * 16;
    const int aoff1 = (warp_m * 32 + 16 + (lane & 15)) * 128 + (lane >> 4) * 16;
    const int boff0 = (warp_n * 32 + 0  + (lane & 15)) * 128 + (lane >> 4) * 16;
    const int boff1 = (warp_n * 32 + 16 + (lane & 15)) * 128 + (lane >> 4) * 16;

    // accumulators (+bias)
    float c[2][4][4];
    {
        const int cb = (int)col0 + warp_n * 32 + 2 * (lane & 3);
#pragma unroll
        for (int tn = 0; tn < 4; tn++) {
            float b0v = bias[cb + tn * 8];
            float b1v = bias[cb + tn * 8 + 1];
#pragma unroll
            for (int tm = 0; tm < 2; tm++) {
                c[tm][tn][0] = b0v; c[tm][tn][1] = b1v;
                c[tm][tn][2] = b0v; c[tm][tn][3] = b1v;
            }
        }
    }

    const int nch = K3 / 64;
    float4 ra[4], rb[2];
#pragma unroll
    for (int q = 0; q < 4; q++) ra[q] = *(const float4*)(Abase + (size_t)q * 32 * K3);
#pragma unroll
    for (int q = 0; q < 2; q++) rb[q] = *(const float4*)(Wbase + (size_t)q * 32 * K3);

    for (int t = 0; t < nch; t++) {
        const int bi = t & 1;
        __syncthreads();
#pragma unroll
        for (int q = 0; q < 4; q++)
            *(float4*)(sA[bi] + sw128((lrow + 32 * q) * 128 + lcol * 16)) = ra[q];
#pragma unroll
        for (int q = 0; q < 2; q++)
            *(float4*)(sB[bi] + sw128((lrow + 32 * q) * 128 + lcol * 16)) = rb[q];
        __syncthreads();

        if (t + 1 < nch) {
            const __nv_bfloat16* Ab = Abase + (t + 1) * 64;
            const __nv_bfloat16* Wb = Wbase + (t + 1) * 64;
#pragma unroll
            for (int q = 0; q < 4; q++) ra[q] = *(const float4*)(Ab + (size_t)q * 32 * K3);
#pragma unroll
            for (int q = 0; q < 2; q++) rb[q] = *(const float4*)(Wb + (size_t)q * 32 * K3);
        }

#pragma unroll
        for (int s = 0; s < 4; s++) {
            uint32_t af[2][4], bf[2][4];
            LDSM_X4(af[0][0], af[0][1], af[0][2], af[0][3], uA[bi] + sw128(aoff0 + s * 32));
            LDSM_X4(af[1][0], af[1][1], af[1][2], af[1][3], uA[bi] + sw128(aoff1 + s * 32));
            // bf[g]: r0 = n(g16+0..7) k0-7, r1 = n(+8..15) k0-7, r2/r3 = same k8-15
            LDSM_X4(bf[0][0], bf[0][1], bf[0][2], bf[0][3], uB[bi] + sw128(boff0 + s * 32));
            LDSM_X4(bf[1][0], bf[1][1], bf[1][2], bf[1][3], uB[bi] + sw128(boff1 + s * 32));
#pragma unroll
            for (int tm = 0; tm < 2; tm++)
#pragma unroll
                for (int g = 0; g < 2; g++)
#pragma unroll
                    for (int h = 0; h < 2; h++)
                        MMA16816(c[tm][g * 2 + h],
                                 af[tm][0], af[tm][1], af[tm][2], af[tm][3],
                                 bf[g][h], bf[g][2 + h]);
        }
    }
    __syncthreads();

    // stage C to smem (stride 66 to break bank conflicts)
#pragma unroll
    for (int tm = 0; tm < 2; tm++) {
        const int rb_ = warp_m * 32 + tm * 16 + (lane >> 2);
#pragma unroll
        for (int tn = 0; tn < 4; tn++) {
            const int cb = warp_n * 32 + tn * 8 + 2 * (lane & 3);
            sepi[rb_ * 66 + cb]           = c[tm][tn][0];
            sepi[rb_ * 66 + cb + 1]       = c[tm][tn][1];
            sepi[(rb_ + 8) * 66 + cb]     = c[tm][tn][2];
            sepi[(rb_ + 8) * 66 + cb + 1] = c[tm][tn][3];
        }
    }
    __syncthreads();

    if (mode == 0) {
        for (int i = tid; i < 128 * GBN; i += 256) {
            int m = i >> 6, j = i & 63;
            Cf[(row0 + m) * (size_t)ldc + col0 + j] = fmaxf(sepi[m * 66 + j], 0.0f);
        }
    } else {
        for (int i = tid; i < 128 * GBN; i += 256) {
            int m = i >> 6, j = i & 63;
            write3a(C3 + (row0 + m) * (size_t)(3 * KpOut), KpOut,
                    (int)col0 + j, fmaxf(sepi[m * 66 + j], 0.0f));
        }
    }
}

// ---------------- embedding gather + interaction -> R triple ---------------
__global__ void __launch_bounds__(256) embed_kernel(
    const void*  __restrict__ lsi_raw,
    const float* __restrict__ emb)
{
    __shared__ float F[NF * FSTR];
    __shared__ int   sidx[NT * LOOKUPS];

    const int b    = blockIdx.x;
    const int tid  = threadIdx.x;
    const int is64 = g_idx64;

    if (tid < NT * LOOKUPS) {
        int t = tid >> 2, l = tid & 3;
        long long off = (long long)t * (BATCH * LOOKUPS) + (long long)b * LOOKUPS + l;
        int idx = is64 ? (int)((const long long*)lsi_raw)[off]
                       : ((const int*)lsi_raw)[off];
        sidx[tid] = idx;
    }
    if (tid < EDIM)
        F[tid] = g_xbot[(size_t)b * EDIM + tid];
    __syncthreads();

    for (int q = tid; q < NT * EDIM; q += 256) {
        int t = q >> 6, d = q & 63;
        const float* base = emb + (size_t)t * TROWS * EDIM;
        float acc = 0.0f;
#pragma unroll
        for (int l = 0; l < LOOKUPS; l++)
            acc += base[(size_t)sidx[t * 4 + l] * EDIM + d];
        F[(t + 1) * FSTR + d] = acc * 0.25f;
    }
    __syncthreads();

    __nv_bfloat16* Rrow = g_Rt + (size_t)b * (3 * RKP);
    if (tid < EDIM) write3a(Rrow, RKP, tid, F[tid]);
    for (int j = RDIM + tid; j < RKP; j += 256) write3a(Rrow, RKP, j, 0.0f);

    for (int p = tid; p < NPAIR; p += 256) {
        int i = (int)((1.0f + sqrtf(1.0f + 8.0f * (float)p)) * 0.5f);
        while (i * (i - 1) / 2 > p) i--;
        while ((i + 1) * i / 2 <= p) i++;
        int j = p - i * (i - 1) / 2;
        const float* Fi = F + i * FSTR;
        const float* Fj = F + j * FSTR;
        float acc = 0.0f;
#pragma unroll 16
        for (int k = 0; k < EDIM; k++) acc += Fi[k] * Fj[k];
        write3a(Rrow, RKP, 64 + p, acc);
    }
}

// ---------------- top layer2: 256 -> 1 (warp per row) ----------------------
__global__ void __launch_bounds__(256) top2_kernel(
    const float* __restrict__ A,
    const float* __restrict__ w, const float* __restrict__ b,
    float* __restrict__ out)
{
    const int warp = threadIdx.x >> 5, lane = threadIdx.x & 31;
    const int row  = blockIdx.x * 8 + warp;
    const float* a = A + (size_t)row * 256;
    float4 a0 = *(const float4*)(a + lane * 4);
    float4 a1 = *(const float4*)(a + 128 + lane * 4);
    float4 w0 = *(const float4*)(w + lane * 4);
    float4 w1 = *(const float4*)(w + 128 + lane * 4);
    float acc = a0.x * w0.x + a0.y * w0.y + a0.z * w0.z + a0.w * w0.w
              + a1.x * w1.x + a1.y * w1.y + a1.z * w1.z + a1.w * w1.w;
#pragma unroll
    for (int o = 16; o; o >>= 1) acc += __shfl_down_sync(0xffffffffu, acc, o);
    if (lane == 0) out[row] = acc + b[0];
}

// ---------------- launch ----------------
extern "C" void kernel_launch(void* const* d_in, const int* in_sizes, int n_in,
                              void* d_out, int out_size)
{
    const float* dense_x = (const float*)d_in[0];
    const void*  lsi     = d_in[2];
    const float* emb     = (const float*)d_in[3];
    const float* bw0 = (const float*)d_in[4];
    const float* bb0 = (const float*)d_in[5];
    const float* bw1 = (const float*)d_in[6];
    const float* bb1 = (const float*)d_in[7];
    const float* bw2 = (const float*)d_in[8];
    const float* bb2 = (const float*)d_in[9];
    const float* tw0 = (const float*)d_in[10];
    const float* tb0 = (const float*)d_in[11];
    const float* tw1 = (const float*)d_in[12];
    const float* tb1 = (const float*)d_in[13];
    const float* tw2 = (const float*)d_in[14];
    const float* tb2 = (const float*)d_in[15];
    float* out = (float*)d_out;

    __nv_bfloat16 *h0t, *a1t, *Rt, *t0t, *wb1t, *wb2t, *wt0t, *wt1t;
    float *xbot, *t1;
    cudaGetSymbolAddress((void**)&h0t,  g_h0t);
    cudaGetSymbolAddress((void**)&a1t,  g_a1t);
    cudaGetSymbolAddress((void**)&Rt,   g_Rt);
    cudaGetSymbolAddress((void**)&t0t,  g_t0t);
    cudaGetSymbolAddress((void**)&wb1t, g_wb1t);
    cudaGetSymbolAddress((void**)&wb2t, g_wb2t);
    cudaGetSymbolAddress((void**)&wt0t, g_wt0t);
    cudaGetSymbolAddress((void**)&wt1t, g_wt1t);
    cudaGetSymbolAddress((void**)&xbot, g_xbot);
    cudaGetSymbolAddress((void**)&t1,   g_t1);

    const int dynsz = 49152 + 1024;
    cudaFuncSetAttribute(gemm_mma, cudaFuncAttributeMaxDynamicSharedMemorySize, dynsz);

    detect_kernel<<<1, 32>>>((const int*)lsi);
    wconv_kernel<<<(256 * 512 + 255) / 256, 256>>>(bw1, 512, 512, 256, wb1t);
    wconv_kernel<<<(64 * 256 + 255) / 256, 256>>>(bw2, 256, 256, 64, wb2t);
    wconv_kernel<<<(512 * RKP + 255) / 256, 256>>>(tw0, RDIM, RKP, 512, wt0t);
    wconv_kernel<<<(256 * 512 + 255) / 256, 256>>>(tw1, 512, 512, 256, wt1t);

    // bottom MLP
    bot0_kernel<<<BATCH / B0_ROWS, 256>>>(dense_x, bw0, bb0);
    gemm_mma<<<dim3(BATCH / 128, 4), 256, dynsz>>>(h0t, wb1t, bb1, 1536,
                                                   nullptr, 0, a1t, 256, 1);
    gemm_mma<<<dim3(BATCH / 128, 1), 256, dynsz>>>(a1t, wb2t, bb2, 768,
                                                   xbot, 64, nullptr, 0, 0);
    // embeddings + interaction -> R triple
    embed_kernel<<<BATCH, 256>>>(lsi, emb);

    // top MLP
    gemm_mma<<<dim3(BATCH / 128, 8), 256, dynsz>>>(Rt, wt0t, tb0, 1344,
                                                   nullptr, 0, t0t, 512, 1);
    gemm_mma<<<dim3(BATCH / 128, 4), 256, dynsz>>>(t0t, wt1t, tb1, 1536,
                                                   t1, 256, nullptr, 0, 0);
    top2_kernel<<<BATCH / 8, 256>>>(t1, tw2, tb2, out);
}

// round 7
// speedup vs baseline: 13.6154x; 1.0954x over previous
#include <cuda_runtime.h>
#include <cuda_bf16.h>
#include <math.h>
#include <stdint.h>

// ---------------- problem constants ----------------
#define NT      26
#define TROWS   100001
#define EDIM    64
#define BATCH   8192
#define LOOKUPS 4
#define NF      27
#define NPAIR   351
#define RDIM    415
#define RKP     448           // top-L0 K padded to multiple of 64
#define FSTR    68

// ---------------- scratch (allocation-free device globals) ----------------
// bf16 [hi|lo] pair buffers, row stride 2*Kp.
__device__ __align__(16) __nv_bfloat16 g_h0[(size_t)BATCH * 1024];  // Kp=512
__device__ __align__(16) __nv_bfloat16 g_a1[(size_t)BATCH * 512];   // Kp=256
__device__ __align__(16) __nv_bfloat16 g_Rp[(size_t)BATCH * 896];   // Kp=448
__device__ __align__(16) __nv_bfloat16 g_t0[(size_t)BATCH * 1024];  // Kp=512
__device__ __align__(16) float g_xbot[(size_t)BATCH * EDIM];
__device__ __align__(16) float g_t1[(size_t)BATCH * 256];
// weight [hi|lo] pairs
__device__ __align__(16) __nv_bfloat16 g_wb1[256 * 1024];
__device__ __align__(16) __nv_bfloat16 g_wb2[64  * 512];
__device__ __align__(16) __nv_bfloat16 g_wt0[512 * 896];
__device__ __align__(16) __nv_bfloat16 g_wt1[256 * 1024];
__device__ int g_idx64;

// ---------------- helpers ----------------
__device__ __forceinline__ uint32_t smem_u32(const void* p) {
    uint32_t a;
    asm("{ .reg .u64 t; cvta.to.shared.u64 t, %1; cvt.u32.u64 %0, t; }" : "=r"(a) : "l"(p));
    return a;
}
__device__ __forceinline__ uint32_t sw128(uint32_t o) { return o ^ ((o >> 3) & 0x70); }

#define LDSM_X4(r0, r1, r2, r3, a) \
    asm volatile("ldmatrix.sync.aligned.m8n8.x4.shared.b16 {%0,%1,%2,%3}, [%4];" \
                 : "=r"(r0), "=r"(r1), "=r"(r2), "=r"(r3) : "r"(a))

#define MMA16816(c, a0, a1, a2, a3, b0, b1) \
    asm volatile("mma.sync.aligned.m16n8k16.row.col.f32.bf16.bf16.f32 " \
                 "{%0,%1,%2,%3},{%4,%5,%6,%7},{%8,%9},{%0,%1,%2,%3};" \
                 : "+f"((c)[0]), "+f"((c)[1]), "+f"((c)[2]), "+f"((c)[3]) \
                 : "r"(a0), "r"(a1), "r"(a2), "r"(a3), "r"(b0), "r"(b1))

// split v into hi/lo bf16, store scalar into [hi|lo] row (stride 2*Kp)
__device__ __forceinline__ void write2(__nv_bfloat16* row, int Kp, int j, float v) {
    __nv_bfloat16 hi = __float2bfloat16(v);
    __nv_bfloat16 lo = __float2bfloat16(v - __bfloat162float(hi));
    row[j] = hi; row[Kp + j] = lo;
}
// store a pair of adjacent outputs as packed bf16x2 hi + lo
__device__ __forceinline__ void store_pair2(__nv_bfloat16* base, int Kp,
                                            float v0, float v1) {
    __nv_bfloat16 h0 = __float2bfloat16(v0);
    __nv_bfloat16 h1 = __float2bfloat16(v1);
    __nv_bfloat16 l0 = __float2bfloat16(v0 - __bfloat162float(h0));
    __nv_bfloat16 l1 = __float2bfloat16(v1 - __bfloat162float(h1));
    *(__nv_bfloat162*)(base)      = __nv_bfloat162(h0, h1);
    *(__nv_bfloat162*)(base + Kp) = __nv_bfloat162(l0, l1);
}

// ---------------- index dtype probe ----------------
__global__ void detect_kernel(const int* __restrict__ lsi_raw) {
    if (threadIdx.x == 0 && blockIdx.x == 0) {
        int ok = 1;
        for (int p = 0; p < 32; p++) {
            int lo = lsi_raw[2 * p], hi = lsi_raw[2 * p + 1];
            if (hi != 0 || (unsigned)lo > 100000u) { ok = 0; break; }
        }
        g_idx64 = ok;
    }
}

// ---------------- merged weight convert (all 4 weight tensors) -------------
#define WC0 (256 * 512)
#define WC1 (64 * 256)
#define WC2 (512 * 448)
#define WC3 (256 * 512)
#define WCTOT (WC0 + WC1 + WC2 + WC3)
__global__ void wconv_all(const float* __restrict__ w1, const float* __restrict__ w2,
                          const float* __restrict__ w3, const float* __restrict__ w4)
{
    int i = blockIdx.x * 256 + threadIdx.x;
    if (i >= WCTOT) return;
    if (i < WC0) {
        int n = i >> 9, k = i & 511;
        write2(g_wb1 + (size_t)n * 1024, 512, k, w1[n * 512 + k]);
    } else if (i < WC0 + WC1) {
        i -= WC0;
        int n = i >> 8, k = i & 255;
        write2(g_wb2 + (size_t)n * 512, 256, k, w2[n * 256 + k]);
    } else if (i < WC0 + WC1 + WC2) {
        i -= WC0 + WC1;
        int n = i / 448, k = i % 448;
        float v = (k < RDIM) ? w3[n * RDIM + k] : 0.0f;
        write2(g_wt0 + (size_t)n * 896, 448, k, v);
    } else {
        i -= WC0 + WC1 + WC2;
        int n = i >> 9, k = i & 511;
        write2(g_wt1 + (size_t)n * 1024, 512, k, w4[n * 512 + k]);
    }
}

// ---------------- bottom layer0: 13 -> 512, pair out -----------------------
#define B0_ROWS 32
__global__ void __launch_bounds__(256) bot0_kernel(
    const float* __restrict__ x,
    const float* __restrict__ w, const float* __restrict__ b)
{
    __shared__ float ws[512 * 13];
    __shared__ float bs[512];
    __shared__ float xs[B0_ROWS * 13];
    const int tid  = threadIdx.x;
    const int row0 = blockIdx.x * B0_ROWS;

    for (int i = tid; i < 512 * 13; i += 256) ws[i] = w[i];
    for (int i = tid; i < 512; i += 256)      bs[i] = b[i];
    for (int i = tid; i < B0_ROWS * 13; i += 256) xs[i] = x[row0 * 13 + i];
    __syncthreads();

    for (int o = tid; o < B0_ROWS * 512; o += 256) {
        int r = o >> 9, j = o & 511;
        float acc = bs[j];
        const float* xr = xs + r * 13;
        const float* wr = ws + j * 13;
#pragma unroll
        for (int k = 0; k < 13; k++) acc += xr[k] * wr[k];
        write2(g_h0 + (size_t)(row0 + r) * 1024, 512, j, fmaxf(acc, 0.0f));
    }
}

// ---------------- mma.sync bf16 GEMM: C = relu(A*W^T + bias) ---------------
// A2/W2: [hi|lo] bf16 pairs, row stride 2*Kp. Logical K-expansion is
// [hi|lo|hi] x [hi|hi|lo] realized by chunk-index remapping (3*nz chunks).
// BM=128, BK=64, BN templated (64/128). 256 threads.
// mode 0: fp32 out Cf[ldc]; mode 1: [hi|lo] pair out C2 (Kp=KpOut).
template<int BN>
__global__ void __launch_bounds__(256) gemm_mma(
    const __nv_bfloat16* __restrict__ A2,
    const __nv_bfloat16* __restrict__ W2,
    const float* __restrict__ bias, int Kp,
    float* __restrict__ Cf, int ldc,
    __nv_bfloat16* __restrict__ C2, int KpOut, int mode)
{
    constexpr int WN  = BN / 32;          // warps along N (2 or 4)
    constexpr int WM  = 8 / WN;           // warps along M (4 or 2)
    constexpr int MT  = 128 / (16 * WM);  // m16 frags per warp (2 or 4)
    constexpr int NBB = BN / 32;          // B float4 loads per thread

    extern __shared__ char dynsm[];
    const int tid  = threadIdx.x;
    const int wid  = tid >> 5;
    const int lane = tid & 31;
    const int warp_m = wid % WM;
    const int warp_n = wid / WM;
    const size_t row0 = (size_t)blockIdx.x * 128;
    const size_t col0 = (size_t)blockIdx.y * BN;

    uint32_t dbase = smem_u32(dynsm);
    uint32_t abase = (dbase + 1023) & ~1023u;
    char* sb = dynsm + (abase - dbase);
    char* sA[2] = { sb, sb + 16384 };
    char* sB[2] = { sb + 32768, sb + 32768 + BN * 128 };
    const uint32_t uA[2] = { abase, abase + 16384 };
    const uint32_t uB[2] = { abase + 32768, abase + 32768 + (uint32_t)BN * 128 };

    const int lrow = tid >> 3;
    const int lcol = tid & 7;
    const int K2 = 2 * Kp;
    const __nv_bfloat16* Abase = A2 + (row0 + lrow) * (size_t)K2 + lcol * 8;
    const __nv_bfloat16* Wbase = W2 + (col0 + lrow) * (size_t)K2 + lcol * 8;

    // ldmatrix byte offsets
    int abyte[MT], bbyte[2];
#pragma unroll
    for (int tm = 0; tm < MT; tm++)
        abyte[tm] = (warp_m * MT * 16 + tm * 16 + (lane & 15)) * 128 + (lane >> 4) * 16;
#pragma unroll
    for (int g = 0; g < 2; g++)
        bbyte[g] = (warp_n * 32 + g * 16 + (lane & 15)) * 128 + (lane >> 4) * 16;

    // accumulators (+bias)
    float c[MT][4][4];
    {
        const int cb = (int)col0 + warp_n * 32 + 2 * (lane & 3);
#pragma unroll
        for (int tn = 0; tn < 4; tn++) {
            float b0v = bias[cb + tn * 8];
            float b1v = bias[cb + tn * 8 + 1];
#pragma unroll
            for (int tm = 0; tm < MT; tm++) {
                c[tm][tn][0] = b0v; c[tm][tn][1] = b1v;
                c[tm][tn][2] = b0v; c[tm][tn][3] = b1v;
            }
        }
    }

    const int nz  = Kp / 64;
    const int nch = 3 * nz;
    float4 ra[4], rb[NBB];
#pragma unroll
    for (int q = 0; q < 4; q++)   ra[q] = *(const float4*)(Abase + (size_t)q * 32 * K2);
#pragma unroll
    for (int q = 0; q < NBB; q++) rb[q] = *(const float4*)(Wbase + (size_t)q * 32 * K2);

    for (int t = 0; t < nch; t++) {
        const int bi = t & 1;
        __syncthreads();
#pragma unroll
        for (int q = 0; q < 4; q++)
            *(float4*)(sA[bi] + sw128((lrow + 32 * q) * 128 + lcol * 16)) = ra[q];
#pragma unroll
        for (int q = 0; q < NBB; q++)
            *(float4*)(sB[bi] + sw128((lrow + 32 * q) * 128 + lcol * 16)) = rb[q];
        __syncthreads();

        if (t + 1 < nch) {
            const int tn1 = t + 1;
            const int at = (tn1 < 2 * nz) ? tn1 : tn1 - 2 * nz;   // A: [hi|lo|hi]
            const int wt = (tn1 < nz)     ? tn1 : tn1 - nz;       // W: [hi|hi|lo]
            const __nv_bfloat16* Ab = Abase + at * 64;
            const __nv_bfloat16* Wb = Wbase + wt * 64;
#pragma unroll
            for (int q = 0; q < 4; q++)   ra[q] = *(const float4*)(Ab + (size_t)q * 32 * K2);
#pragma unroll
            for (int q = 0; q < NBB; q++) rb[q] = *(const float4*)(Wb + (size_t)q * 32 * K2);
        }

#pragma unroll
        for (int s = 0; s < 4; s++) {
            uint32_t af[MT][4], bf[2][4];
#pragma unroll
            for (int tm = 0; tm < MT; tm++)
                LDSM_X4(af[tm][0], af[tm][1], af[tm][2], af[tm][3],
                        uA[bi] + sw128(abyte[tm] + s * 32));
#pragma unroll
            for (int g = 0; g < 2; g++)
                LDSM_X4(bf[g][0], bf[g][1], bf[g][2], bf[g][3],
                        uB[bi] + sw128(bbyte[g] + s * 32));
#pragma unroll
            for (int tm = 0; tm < MT; tm++)
#pragma unroll
                for (int g = 0; g < 2; g++)
#pragma unroll
                    for (int h = 0; h < 2; h++)
                        MMA16816(c[tm][g * 2 + h],
                                 af[tm][0], af[tm][1], af[tm][2], af[tm][3],
                                 bf[g][h], bf[g][2 + h]);
        }
    }

    // epilogue: fragments straight to global (packed pair stores)
#pragma unroll
    for (int tm = 0; tm < MT; tm++) {
        const size_t r = row0 + warp_m * MT * 16 + tm * 16 + (lane >> 2);
#pragma unroll
        for (int tn = 0; tn < 4; tn++) {
            const size_t cc = col0 + warp_n * 32 + tn * 8 + 2 * (lane & 3);
            float v0 = fmaxf(c[tm][tn][0], 0.0f);
            float v1 = fmaxf(c[tm][tn][1], 0.0f);
            float v2 = fmaxf(c[tm][tn][2], 0.0f);
            float v3 = fmaxf(c[tm][tn][3], 0.0f);
            if (mode == 0) {
                *(float2*)(Cf + r * ldc + cc)       = make_float2(v0, v1);
                *(float2*)(Cf + (r + 8) * ldc + cc) = make_float2(v2, v3);
            } else {
                store_pair2(C2 + r * (size_t)(2 * KpOut) + cc,       KpOut, v0, v1);
                store_pair2(C2 + (r + 8) * (size_t)(2 * KpOut) + cc, KpOut, v2, v3);
            }
        }
    }
}

// ---------------- embedding gather + interaction -> R pair -----------------
__global__ void __launch_bounds__(256) embed_kernel(
    const void*  __restrict__ lsi_raw,
    const float* __restrict__ emb)
{
    __shared__ __align__(16) float F[NF * FSTR];
    __shared__ int sidx[NT * LOOKUPS];

    const int b    = blockIdx.x;
    const int tid  = threadIdx.x;
    const int is64 = g_idx64;

    if (tid < NT * LOOKUPS) {
        int t = tid >> 2, l = tid & 3;
        long long off = (long long)t * (BATCH * LOOKUPS) + (long long)b * LOOKUPS + l;
        int idx = is64 ? (int)((const long long*)lsi_raw)[off]
                       : ((const int*)lsi_raw)[off];
        sidx[tid] = idx;
    }
    if (tid < EDIM)
        F[tid] = g_xbot[(size_t)b * EDIM + tid];
    __syncthreads();

    // vectorized gather: 26 tables x 16 float4 = 416 items
    for (int q = tid; q < NT * 16; q += 256) {
        int t = q >> 4, v = q & 15;
        const float4* base = (const float4*)(emb + (size_t)t * TROWS * EDIM) + v;
        float4 acc = make_float4(0.f, 0.f, 0.f, 0.f);
#pragma unroll
        for (int l = 0; l < LOOKUPS; l++) {
            float4 e = base[(size_t)sidx[t * 4 + l] * 16];
            acc.x += e.x; acc.y += e.y; acc.z += e.z; acc.w += e.w;
        }
        acc.x *= 0.25f; acc.y *= 0.25f; acc.z *= 0.25f; acc.w *= 0.25f;
        *(float4*)(F + (t + 1) * FSTR + v * 4) = acc;
    }
    __syncthreads();

    __nv_bfloat16* Rrow = g_Rp + (size_t)b * 896;
    if (tid < EDIM) write2(Rrow, RKP, tid, F[tid]);
    for (int j = RDIM + tid; j < RKP; j += 256) write2(Rrow, RKP, j, 0.0f);

    for (int p = tid; p < NPAIR; p += 256) {
        int i = (int)((1.0f + sqrtf(1.0f + 8.0f * (float)p)) * 0.5f);
        while (i * (i - 1) / 2 > p) i--;
        while ((i + 1) * i / 2 <= p) i++;
        int j = p - i * (i - 1) / 2;
        const float* Fi = F + i * FSTR;
        const float* Fj = F + j * FSTR;
        float acc = 0.0f;
#pragma unroll 16
        for (int k = 0; k < EDIM; k++) acc += Fi[k] * Fj[k];
        write2(Rrow, RKP, 64 + p, acc);
    }
}

// ---------------- top layer2: 256 -> 1 (warp per row) ----------------------
__global__ void __launch_bounds__(256) top2_kernel(
    const float* __restrict__ A,
    const float* __restrict__ w, const float* __restrict__ b,
    float* __restrict__ out)
{
    const int warp = threadIdx.x >> 5, lane = threadIdx.x & 31;
    const int row  = blockIdx.x * 8 + warp;
    const float* a = A + (size_t)row * 256;
    float4 a0 = *(const float4*)(a + lane * 4);
    float4 a1 = *(const float4*)(a + 128 + lane * 4);
    float4 w0 = *(const float4*)(w + lane * 4);
    float4 w1 = *(const float4*)(w + 128 + lane * 4);
    float acc = a0.x * w0.x + a0.y * w0.y + a0.z * w0.z + a0.w * w0.w
              + a1.x * w1.x + a1.y * w1.y + a1.z * w1.z + a1.w * w1.w;
#pragma unroll
    for (int o = 16; o; o >>= 1) acc += __shfl_down_sync(0xffffffffu, acc, o);
    if (lane == 0) out[row] = acc + b[0];
}

// ---------------- launch ----------------
extern "C" void kernel_launch(void* const* d_in, const int* in_sizes, int n_in,
                              void* d_out, int out_size)
{
    const float* dense_x = (const float*)d_in[0];
    const void*  lsi     = d_in[2];
    const float* emb     = (const float*)d_in[3];
    const float* bw0 = (const float*)d_in[4];
    const float* bb0 = (const float*)d_in[5];
    const float* bw1 = (const float*)d_in[6];
    const float* bb1 = (const float*)d_in[7];
    const float* bw2 = (const float*)d_in[8];
    const float* bb2 = (const float*)d_in[9];
    const float* tw0 = (const float*)d_in[10];
    const float* tb0 = (const float*)d_in[11];
    const float* tw1 = (const float*)d_in[12];
    const float* tb1 = (const float*)d_in[13];
    const float* tw2 = (const float*)d_in[14];
    const float* tb2 = (const float*)d_in[15];
    float* out = (float*)d_out;

    __nv_bfloat16 *h0, *a1, *Rp, *t0, *wb1, *wb2, *wt0, *wt1;
    float *xbot, *t1;
    cudaGetSymbolAddress((void**)&h0,  g_h0);
    cudaGetSymbolAddress((void**)&a1,  g_a1);
    cudaGetSymbolAddress((void**)&Rp,  g_Rp);
    cudaGetSymbolAddress((void**)&t0,  g_t0);
    cudaGetSymbolAddress((void**)&wb1, g_wb1);
    cudaGetSymbolAddress((void**)&wb2, g_wb2);
    cudaGetSymbolAddress((void**)&wt0, g_wt0);
    cudaGetSymbolAddress((void**)&wt1, g_wt1);
    cudaGetSymbolAddress((void**)&xbot, g_xbot);
    cudaGetSymbolAddress((void**)&t1,   g_t1);

    const int dyn128 = 1024 + 32768 + 2 * 128 * 128;   // 66560
    const int dyn64  = 1024 + 32768 + 2 * 64 * 128;    // 50176
    cudaFuncSetAttribute(gemm_mma<128>, cudaFuncAttributeMaxDynamicSharedMemorySize, dyn128);
    cudaFuncSetAttribute(gemm_mma<64>,  cudaFuncAttributeMaxDynamicSharedMemorySize, dyn64);

    detect_kernel<<<1, 32>>>((const int*)lsi);
    wconv_all<<<(WCTOT + 255) / 256, 256>>>(bw1, bw2, tw0, tw1);

    // bottom MLP
    bot0_kernel<<<BATCH / B0_ROWS, 256>>>(dense_x, bw0, bb0);
    gemm_mma<128><<<dim3(BATCH / 128, 2), 256, dyn128>>>(h0, wb1, bb1, 512,
                                                         nullptr, 0, a1, 256, 1);
    gemm_mma<64><<<dim3(BATCH / 128, 1), 256, dyn64>>>(a1, wb2, bb2, 256,
                                                       xbot, 64, nullptr, 0, 0);
    // embeddings + interaction -> R pair
    embed_kernel<<<BATCH, 256>>>(lsi, emb);

    // top MLP
    gemm_mma<128><<<dim3(BATCH / 128, 4), 256, dyn128>>>(Rp, wt0, tb0, 448,
                                                         nullptr, 0, t0, 512, 1);
    gemm_mma<128><<<dim3(BATCH / 128, 2), 256, dyn128>>>(t0, wt1, tb1, 512,
                                                         t1, 256, nullptr, 0, 0);
    top2_kernel<<<BATCH / 8, 256>>>(t1, tw2, tb2, out);
}

// round 9
// speedup vs baseline: 17.0895x; 1.2552x over previous
#include <cuda_runtime.h>
#include <cuda_bf16.h>
#include <math.h>
#include <stdint.h>

// ---------------- problem constants ----------------
#define NT      26
#define TROWS   100001
#define EDIM    64
#define BATCH   8192
#define LOOKUPS 4
#define NF      27
#define NPAIR   351
#define RDIM    415
#define RKP     448
#define FSTR    68

// ---------------- scratch (allocation-free device globals) ----------------
// bf16 [hi|lo] pair buffers, row stride 2*Kp.
__device__ __align__(16) __nv_bfloat16 g_h0[(size_t)BATCH * 1024];  // Kp=512
__device__ __align__(16) __nv_bfloat16 g_a1[(size_t)BATCH * 512];   // Kp=256
__device__ __align__(16) __nv_bfloat16 g_Rp[(size_t)BATCH * 896];   // Kp=448
__device__ __align__(16) __nv_bfloat16 g_t0[(size_t)BATCH * 1024];  // Kp=512
__device__ __align__(16) float g_xbot[(size_t)BATCH * EDIM];
__device__ __align__(16) float g_t1[(size_t)BATCH * 256];
// weight [hi|lo] pairs
__device__ __align__(16) __nv_bfloat16 g_wb1[256 * 1024];
__device__ __align__(16) __nv_bfloat16 g_wb2[64  * 512];
__device__ __align__(16) __nv_bfloat16 g_wt0[512 * 896];
__device__ __align__(16) __nv_bfloat16 g_wt1[256 * 1024];
__device__ int g_idx64;

// ---------------- helpers ----------------
__device__ __forceinline__ uint32_t smem_u32(const void* p) {
    uint32_t a;
    asm("{ .reg .u64 t; cvta.to.shared.u64 t, %1; cvt.u32.u64 %0, t; }" : "=r"(a) : "l"(p));
    return a;
}
__device__ __forceinline__ uint32_t sw128(uint32_t o) { return o ^ ((o >> 3) & 0x70); }

#define CP_ASYNC16(dst, src) \
    asm volatile("cp.async.cg.shared.global [%0], [%1], 16;" :: "r"(dst), "l"(src))
#define CP_COMMIT() asm volatile("cp.async.commit_group;" ::: "memory")
#define CP_WAIT(n)  asm volatile("cp.async.wait_group %0;" :: "n"(n) : "memory")

#define LDSM_X4(r0, r1, r2, r3, a) \
    asm volatile("ldmatrix.sync.aligned.m8n8.x4.shared.b16 {%0,%1,%2,%3}, [%4];" \
                 : "=r"(r0), "=r"(r1), "=r"(r2), "=r"(r3) : "r"(a))

#define MMA16816(c, a0, a1, a2, a3, b0, b1) \
    asm volatile("mma.sync.aligned.m16n8k16.row.col.f32.bf16.bf16.f32 " \
                 "{%0,%1,%2,%3},{%4,%5,%6,%7},{%8,%9},{%0,%1,%2,%3};" \
                 : "+f"((c)[0]), "+f"((c)[1]), "+f"((c)[2]), "+f"((c)[3]) \
                 : "r"(a0), "r"(a1), "r"(a2), "r"(a3), "r"(b0), "r"(b1))

__device__ __forceinline__ void write2(__nv_bfloat16* row, int Kp, int j, float v) {
    __nv_bfloat16 hi = __float2bfloat16(v);
    __nv_bfloat16 lo = __float2bfloat16(v - __bfloat162float(hi));
    row[j] = hi; row[Kp + j] = lo;
}
__device__ __forceinline__ void store_pair2(__nv_bfloat16* base, int Kp,
                                            float v0, float v1) {
    __nv_bfloat16 h0 = __float2bfloat16(v0);
    __nv_bfloat16 h1 = __float2bfloat16(v1);
    __nv_bfloat16 l0 = __float2bfloat16(v0 - __bfloat162float(h0));
    __nv_bfloat16 l1 = __float2bfloat16(v1 - __bfloat162float(h1));
    *(__nv_bfloat162*)(base)      = __nv_bfloat162(h0, h1);
    *(__nv_bfloat162*)(base + Kp) = __nv_bfloat162(l0, l1);
}

// ---------------- index dtype probe ----------------
__global__ void detect_kernel(const int* __restrict__ lsi_raw) {
    if (threadIdx.x == 0 && blockIdx.x == 0) {
        int ok = 1;
        for (int p = 0; p < 32; p++) {
            int lo = lsi_raw[2 * p], hi = lsi_raw[2 * p + 1];
            if (hi != 0 || (unsigned)lo > 100000u) { ok = 0; break; }
        }
        g_idx64 = ok;
    }
}

// ---------------- merged weight convert -----------------------------------
#define WC0 (256 * 512)
#define WC1 (64 * 256)
#define WC2 (512 * 448)
#define WC3 (256 * 512)
#define WCTOT (WC0 + WC1 + WC2 + WC3)
__global__ void wconv_all(const float* __restrict__ w1, const float* __restrict__ w2,
                          const float* __restrict__ w3, const float* __restrict__ w4)
{
    int i = blockIdx.x * 256 + threadIdx.x;
    if (i >= WCTOT) return;
    if (i < WC0) {
        int n = i >> 9, k = i & 511;
        write2(g_wb1 + (size_t)n * 1024, 512, k, w1[n * 512 + k]);
    } else if (i < WC0 + WC1) {
        i -= WC0;
        int n = i >> 8, k = i & 255;
        write2(g_wb2 + (size_t)n * 512, 256, k, w2[n * 256 + k]);
    } else if (i < WC0 + WC1 + WC2) {
        i -= WC0 + WC1;
        int n = i / 448, k = i % 448;
        float v = (k < RDIM) ? w3[n * RDIM + k] : 0.0f;
        write2(g_wt0 + (size_t)n * 896, 448, k, v);
    } else {
        i -= WC0 + WC1 + WC2;
        int n = i >> 9, k = i & 511;
        write2(g_wt1 + (size_t)n * 1024, 512, k, w4[n * 512 + k]);
    }
}

// ---------------- bottom layer0: 13 -> 512, pair out -----------------------
#define B0_ROWS 32
__global__ void __launch_bounds__(256) bot0_kernel(
    const float* __restrict__ x,
    const float* __restrict__ w, const float* __restrict__ b)
{
    __shared__ float ws[512 * 13];
    __shared__ float bs[512];
    __shared__ float xs[B0_ROWS * 13];
    const int tid  = threadIdx.x;
    const int row0 = blockIdx.x * B0_ROWS;

    for (int i = tid; i < 512 * 13; i += 256) ws[i] = w[i];
    for (int i = tid; i < 512; i += 256)      bs[i] = b[i];
    for (int i = tid; i < B0_ROWS * 13; i += 256) xs[i] = x[row0 * 13 + i];
    __syncthreads();

    for (int o = tid; o < B0_ROWS * 512; o += 256) {
        int r = o >> 9, j = o & 511;
        float acc = bs[j];
        const float* xr = xs + r * 13;
        const float* wr = ws + j * 13;
#pragma unroll
        for (int k = 0; k < 13; k++) acc += xr[k] * wr[k];
        write2(g_h0 + (size_t)(row0 + r) * 1024, 512, j, fmaxf(acc, 0.0f));
    }
}

// ---------------- mma.sync bf16 GEMM, 3-stage cp.async ---------------------
// A2/W2: [hi|lo] pairs, stride 2*Kp; logical [hi|lo|hi]x[hi|hi|lo] via chunk
// remap. BM in {128,64}, BN=64, BK=64. 256 threads: 4(M)x2(N) warps.
// mode 0: fp32 out Cf[ldc]; mode 1: [hi|lo] pair out C2 (Kp=KpOut).
#define NSTAGE 3
template<int BM>
__global__ void __launch_bounds__(256, (BM == 128 ? 2 : 3)) gemm_mma(
    const __nv_bfloat16* __restrict__ A2,
    const __nv_bfloat16* __restrict__ W2,
    const float* __restrict__ bias, int Kp,
    float* __restrict__ Cf, int ldc,
    __nv_bfloat16* __restrict__ C2, int KpOut, int mode)
{
    constexpr int MT     = BM / 64;          // m16 frags per warp
    constexpr int NBA    = BM / 32;          // A cp.async per thread
    constexpr int ABYTES = BM * 128;
    constexpr int STAGEB = ABYTES + 64 * 128;

    extern __shared__ char dynsm[];
    const int tid  = threadIdx.x;
    const int wid  = tid >> 5;
    const int lane = tid & 31;
    const int warp_m = wid & 3;
    const int warp_n = wid >> 2;
    const size_t row0 = (size_t)blockIdx.x * BM;
    const size_t col0 = (size_t)blockIdx.y * 64;

    uint32_t dbase = smem_u32(dynsm);
    uint32_t abase = (dbase + 1023) & ~1023u;
    uint32_t uS[NSTAGE];
#pragma unroll
    for (int s = 0; s < NSTAGE; s++) uS[s] = abase + s * STAGEB;

    const int lrow = tid >> 3;
    const int lcol = tid & 7;
    const int K2 = 2 * Kp;
    const int nz  = Kp / 64;
    const int nch = 3 * nz;
    const __nv_bfloat16* Abase = A2 + (row0 + lrow) * (size_t)K2 + lcol * 8;
    const __nv_bfloat16* Wbase = W2 + (col0 + lrow) * (size_t)K2 + lcol * 8;
    const uint32_t adst = sw128(lrow * 128 + lcol * 16);   // row-q adds 32*128

    // issue chunk t's loads into stage s
    auto issue = [&](int t, int s) {
        const int at = (t < 2 * nz) ? t : t - 2 * nz;      // A: [hi|lo|hi]
        const int wt = (t < nz)     ? t : t - nz;          // W: [hi|hi|lo]
        const __nv_bfloat16* Ab = Abase + at * 64;
        const __nv_bfloat16* Wb = Wbase + wt * 64;
#pragma unroll
        for (int q = 0; q < NBA; q++)
            CP_ASYNC16(uS[s] + adst + q * 32 * 128, Ab + (size_t)q * 32 * K2);
#pragma unroll
        for (int q = 0; q < 2; q++)
            CP_ASYNC16(uS[s] + ABYTES + adst + q * 32 * 128, Wb + (size_t)q * 32 * K2);
    };

    // ldmatrix lane offsets (relative to stage base)
    int abyte[MT], bbyte[2];
#pragma unroll
    for (int tm = 0; tm < MT; tm++)
        abyte[tm] = (warp_m * MT * 16 + tm * 16 + (lane & 15)) * 128 + (lane >> 4) * 16;
#pragma unroll
    for (int g = 0; g < 2; g++)
        bbyte[g] = (warp_n * 32 + g * 16 + (lane & 15)) * 128 + (lane >> 4) * 16;

    // accumulators (+bias)
    float c[MT][4][4];
    {
        const int cb = (int)col0 + warp_n * 32 + 2 * (lane & 3);
#pragma unroll
        for (int tn = 0; tn < 4; tn++) {
            float b0v = bias[cb + tn * 8];
            float b1v = bias[cb + tn * 8 + 1];
#pragma unroll
            for (int tm = 0; tm < MT; tm++) {
                c[tm][tn][0] = b0v; c[tm][tn][1] = b1v;
                c[tm][tn][2] = b0v; c[tm][tn][3] = b1v;
            }
        }
    }

    // prologue: stages 0,1 in flight
    issue(0, 0); CP_COMMIT();
    issue(1, 1); CP_COMMIT();

    for (int t = 0; t < nch; t++) {
        __syncthreads();                       // all warps done with stage (t+2)%3
        if (t + 2 < nch) { issue(t + 2, (t + 2) % NSTAGE); CP_COMMIT(); }
        const int rem = nch - 1 - t;
        if (rem >= 2)      CP_WAIT(2);
        else if (rem == 1) CP_WAIT(1);
        else               CP_WAIT(0);
        __syncthreads();                       // stage t visible to all warps

        const uint32_t sbase = uS[t % NSTAGE];
        const uint32_t bbase = sbase + ABYTES;
#pragma unroll
        for (int s = 0; s < 4; s++) {
            uint32_t af[MT][4], bf[2][4];
#pragma unroll
            for (int tm = 0; tm < MT; tm++)
                LDSM_X4(af[tm][0], af[tm][1], af[tm][2], af[tm][3],
                        sbase + sw128(abyte[tm] + s * 32));
#pragma unroll
            for (int g = 0; g < 2; g++)
                LDSM_X4(bf[g][0], bf[g][1], bf[g][2], bf[g][3],
                        bbase + sw128(bbyte[g] + s * 32));
#pragma unroll
            for (int tm = 0; tm < MT; tm++)
#pragma unroll
                for (int g = 0; g < 2; g++)
#pragma unroll
                    for (int h = 0; h < 2; h++)
                        MMA16816(c[tm][g * 2 + h],
                                 af[tm][0], af[tm][1], af[tm][2], af[tm][3],
                                 bf[g][h], bf[g][2 + h]);
        }
    }

    // epilogue: fragments straight to global
#pragma unroll
    for (int tm = 0; tm < MT; tm++) {
        const size_t r = row0 + warp_m * MT * 16 + tm * 16 + (lane >> 2);
#pragma unroll
        for (int tn = 0; tn < 4; tn++) {
            const size_t cc = col0 + warp_n * 32 + tn * 8 + 2 * (lane & 3);
            float v0 = fmaxf(c[tm][tn][0], 0.0f);
            float v1 = fmaxf(c[tm][tn][1], 0.0f);
            float v2 = fmaxf(c[tm][tn][2], 0.0f);
            float v3 = fmaxf(c[tm][tn][3], 0.0f);
            if (mode == 0) {
                *(float2*)(Cf + r * ldc + cc)       = make_float2(v0, v1);
                *(float2*)(Cf + (r + 8) * ldc + cc) = make_float2(v2, v3);
            } else {
                store_pair2(C2 + r * (size_t)(2 * KpOut) + cc,       KpOut, v0, v1);
                store_pair2(C2 + (r + 8) * (size_t)(2 * KpOut) + cc, KpOut, v2, v3);
            }
        }
    }
}

// ---------------- embedding gather + interaction -> R pair -----------------
__global__ void __launch_bounds__(256) embed_kernel(
    const void*  __restrict__ lsi_raw,
    const float* __restrict__ emb)
{
    __shared__ __align__(16) float F[NF * FSTR];
    __shared__ int sidx[NT * LOOKUPS];

    const int b    = blockIdx.x;
    const int tid  = threadIdx.x;
    const int is64 = g_idx64;

    if (tid < NT * LOOKUPS) {
        int t = tid >> 2, l = tid & 3;
        long long off = (long long)t * (BATCH * LOOKUPS) + (long long)b * LOOKUPS + l;
        int idx = is64 ? (int)((const long long*)lsi_raw)[off]
                       : ((const int*)lsi_raw)[off];
        sidx[tid] = idx;
    }
    if (tid < EDIM)
        F[tid] = g_xbot[(size_t)b * EDIM + tid];
    __syncthreads();

    for (int q = tid; q < NT * 16; q += 256) {
        int t = q >> 4, v = q & 15;
        const float4* base = (const float4*)(emb + (size_t)t * TROWS * EDIM) + v;
        float4 acc = make_float4(0.f, 0.f, 0.f, 0.f);
#pragma unroll
        for (int l = 0; l < LOOKUPS; l++) {
            float4 e = base[(size_t)sidx[t * 4 + l] * 16];
            acc.x += e.x; acc.y += e.y; acc.z += e.z; acc.w += e.w;
        }
        acc.x *= 0.25f; acc.y *= 0.25f; acc.z *= 0.25f; acc.w *= 0.25f;
        *(float4*)(F + (t + 1) * FSTR + v * 4) = acc;
    }
    __syncthreads();

    __nv_bfloat16* Rrow = g_Rp + (size_t)b * 896;
    if (tid < EDIM) write2(Rrow, RKP, tid, F[tid]);
    for (int j = RDIM + tid; j < RKP; j += 256) write2(Rrow, RKP, j, 0.0f);

    for (int p = tid; p < NPAIR; p += 256) {
        int i = (int)((1.0f + sqrtf(1.0f + 8.0f * (float)p)) * 0.5f);
        while (i * (i - 1) / 2 > p) i--;
        while ((i + 1) * i / 2 <= p) i++;
        int j = p - i * (i - 1) / 2;
        const float* Fi = F + i * FSTR;
        const float* Fj = F + j * FSTR;
        float acc = 0.0f;
#pragma unroll 16
        for (int k = 0; k < EDIM; k++) acc += Fi[k] * Fj[k];
        write2(Rrow, RKP, 64 + p, acc);
    }
}

// ---------------- top layer2: 256 -> 1 (warp per row) ----------------------
__global__ void __launch_bounds__(256) top2_kernel(
    const float* __restrict__ A,
    const float* __restrict__ w, const float* __restrict__ b,
    float* __restrict__ out)
{
    const int warp = threadIdx.x >> 5, lane = threadIdx.x & 31;
    const int row  = blockIdx.x * 8 + warp;
    const float* a = A + (size_t)row * 256;
    float4 a0 = *(const float4*)(a + lane * 4);
    float4 a1 = *(const float4*)(a + 128 + lane * 4);
    float4 w0 = *(const float4*)(w + lane * 4);
    float4 w1 = *(const float4*)(w + 128 + lane * 4);
    float acc = a0.x * w0.x + a0.y * w0.y + a0.z * w0.z + a0.w * w0.w
              + a1.x * w1.x + a1.y * w1.y + a1.z * w1.z + a1.w * w1.w;
#pragma unroll
    for (int o = 16; o; o >>= 1) acc += __shfl_down_sync(0xffffffffu, acc, o);
    if (lane == 0) out[row] = acc + b[0];
}

// ---------------- launch ----------------
extern "C" void kernel_launch(void* const* d_in, const int* in_sizes, int n_in,
                              void* d_out, int out_size)
{
    const float* dense_x = (const float*)d_in[0];
    const void*  lsi     = d_in[2];
    const float* emb     = (const float*)d_in[3];
    const float* bw0 = (const float*)d_in[4];
    const float* bb0 = (const float*)d_in[5];
    const float* bw1 = (const float*)d_in[6];
    const float* bb1 = (const float*)d_in[7];
    const float* bw2 = (const float*)d_in[8];
    const float* bb2 = (const float*)d_in[9];
    const float* tw0 = (const float*)d_in[10];
    const float* tb0 = (const float*)d_in[11];
    const float* tw1 = (const float*)d_in[12];
    const float* tb1 = (const float*)d_in[13];
    const float* tw2 = (const float*)d_in[14];
    const float* tb2 = (const float*)d_in[15];
    float* out = (float*)d_out;

    __nv_bfloat16 *h0, *a1, *Rp, *t0, *wb1, *wb2, *wt0, *wt1;
    float *xbot, *t1;
    cudaGetSymbolAddress((void**)&h0,  g_h0);
    cudaGetSymbolAddress((void**)&a1,  g_a1);
    cudaGetSymbolAddress((void**)&Rp,  g_Rp);
    cudaGetSymbolAddress((void**)&t0,  g_t0);
    cudaGetSymbolAddress((void**)&wb1, g_wb1);
    cudaGetSymbolAddress((void**)&wb2, g_wb2);
    cudaGetSymbolAddress((void**)&wt0, g_wt0);
    cudaGetSymbolAddress((void**)&wt1, g_wt1);
    cudaGetSymbolAddress((void**)&xbot, g_xbot);
    cudaGetSymbolAddress((void**)&t1,   g_t1);

    const int dyn128 = 1024 + NSTAGE * (128 * 128 + 64 * 128);  // 74752
    const int dyn64  = 1024 + NSTAGE * (64 * 128 + 64 * 128);   // 50176
    cudaFuncSetAttribute(gemm_mma<128>, cudaFuncAttributeMaxDynamicSharedMemorySize, dyn128);
    cudaFuncSetAttribute(gemm_mma<64>,  cudaFuncAttributeMaxDynamicSharedMemorySize, dyn64);

    detect_kernel<<<1, 32>>>((const int*)lsi);
    wconv_all<<<(WCTOT + 255) / 256, 256>>>(bw1, bw2, tw0, tw1);

    // bottom MLP
    bot0_kernel<<<BATCH / B0_ROWS, 256>>>(dense_x, bw0, bb0);
    gemm_mma<128><<<dim3(BATCH / 128, 4), 256, dyn128>>>(h0, wb1, bb1, 512,
                                                         nullptr, 0, a1, 256, 1);
    gemm_mma<64><<<dim3(BATCH / 64, 1), 256, dyn64>>>(a1, wb2, bb2, 256,
                                                      xbot, 64, nullptr, 0, 0);
    // embeddings + interaction -> R pair
    embed_kernel<<<BATCH, 256>>>(lsi, emb);

    // top MLP
    gemm_mma<128><<<dim3(BATCH / 128, 8), 256, dyn128>>>(Rp, wt0, tb0, 448,
                                                         nullptr, 0, t0, 512, 1);
    gemm_mma<128><<<dim3(BATCH / 128, 4), 256, dyn128>>>(t0, wt1, tb1, 512,
                                                         t1, 256, nullptr, 0, 0);
    top2_kernel<<<BATCH / 8, 256>>>(t1, tw2, tb2, out);
}

// round 10
// speedup vs baseline: 18.5377x; 1.0847x over previous
#include <cuda_runtime.h>
#include <cuda_bf16.h>
#include <math.h>
#include <stdint.h>

// ---------------- problem constants ----------------
#define NT      26
#define TROWS   100001
#define EDIM    64
#define BATCH   8192
#define LOOKUPS 4
#define NF      27
#define NPAIR   351
#define RDIM    415
#define RKP     448
#define FSTR    68

// ---------------- scratch (allocation-free device globals) ----------------
// bf16 [hi|lo] pair buffers, row stride 2*Kp.
__device__ __align__(16) __nv_bfloat16 g_h0[(size_t)BATCH * 1024];  // Kp=512
__device__ __align__(16) __nv_bfloat16 g_a1[(size_t)BATCH * 512];   // Kp=256
__device__ __align__(16) __nv_bfloat16 g_Rp[(size_t)BATCH * 896];   // Kp=448
__device__ __align__(16) __nv_bfloat16 g_t0[(size_t)BATCH * 1024];  // Kp=512
__device__ __align__(16) float g_xbot[(size_t)BATCH * EDIM];
__device__ __align__(16) float g_t1[(size_t)BATCH * 256];
// weight [hi|lo] pairs
__device__ __align__(16) __nv_bfloat16 g_wb1[256 * 1024];
__device__ __align__(16) __nv_bfloat16 g_wb2[64  * 512];
__device__ __align__(16) __nv_bfloat16 g_wt0[512 * 896];
__device__ __align__(16) __nv_bfloat16 g_wt1[256 * 1024];
__device__ int g_idx64;

// ---------------- helpers ----------------
__device__ __forceinline__ uint32_t smem_u32(const void* p) {
    uint32_t a;
    asm("{ .reg .u64 t; cvta.to.shared.u64 t, %1; cvt.u32.u64 %0, t; }" : "=r"(a) : "l"(p));
    return a;
}
__device__ __forceinline__ uint32_t sw128(uint32_t o) { return o ^ ((o >> 3) & 0x70); }

#define CP_ASYNC16(dst, src) \
    asm volatile("cp.async.cg.shared.global [%0], [%1], 16;" :: "r"(dst), "l"(src))
#define CP_COMMIT() asm volatile("cp.async.commit_group;" ::: "memory")
#define CP_WAIT(n)  asm volatile("cp.async.wait_group %0;" :: "n"(n) : "memory")

#define LDSM_X4(r0, r1, r2, r3, a) \
    asm volatile("ldmatrix.sync.aligned.m8n8.x4.shared.b16 {%0,%1,%2,%3}, [%4];" \
                 : "=r"(r0), "=r"(r1), "=r"(r2), "=r"(r3) : "r"(a))

#define MMA16816(c, a0, a1, a2, a3, b0, b1) \
    asm volatile("mma.sync.aligned.m16n8k16.row.col.f32.bf16.bf16.f32 " \
                 "{%0,%1,%2,%3},{%4,%5,%6,%7},{%8,%9},{%0,%1,%2,%3};" \
                 : "+f"((c)[0]), "+f"((c)[1]), "+f"((c)[2]), "+f"((c)[3]) \
                 : "r"(a0), "r"(a1), "r"(a2), "r"(a3), "r"(b0), "r"(b1))

__device__ __forceinline__ void write2(__nv_bfloat16* row, int Kp, int j, float v) {
    __nv_bfloat16 hi = __float2bfloat16(v);
    __nv_bfloat16 lo = __float2bfloat16(v - __bfloat162float(hi));
    row[j] = hi; row[Kp + j] = lo;
}
__device__ __forceinline__ void store_pair2(__nv_bfloat16* base, int Kp,
                                            float v0, float v1) {
    __nv_bfloat16 h0 = __float2bfloat16(v0);
    __nv_bfloat16 h1 = __float2bfloat16(v1);
    __nv_bfloat16 l0 = __float2bfloat16(v0 - __bfloat162float(h0));
    __nv_bfloat16 l1 = __float2bfloat16(v1 - __bfloat162float(h1));
    *(__nv_bfloat162*)(base)      = __nv_bfloat162(h0, h1);
    *(__nv_bfloat162*)(base + Kp) = __nv_bfloat162(l0, l1);
}

// ---------------- index dtype probe ----------------
__global__ void detect_kernel(const int* __restrict__ lsi_raw) {
    if (threadIdx.x == 0 && blockIdx.x == 0) {
        int ok = 1;
        for (int p = 0; p < 32; p++) {
            int lo = lsi_raw[2 * p], hi = lsi_raw[2 * p + 1];
            if (hi != 0 || (unsigned)lo > 100000u) { ok = 0; break; }
        }
        g_idx64 = ok;
    }
}

// ---------------- merged weight convert -----------------------------------
#define WC0 (256 * 512)
#define WC1 (64 * 256)
#define WC2 (512 * 448)
#define WC3 (256 * 512)
#define WCTOT (WC0 + WC1 + WC2 + WC3)
__global__ void wconv_all(const float* __restrict__ w1, const float* __restrict__ w2,
                          const float* __restrict__ w3, const float* __restrict__ w4)
{
    int i = blockIdx.x * 256 + threadIdx.x;
    if (i >= WCTOT) return;
    if (i < WC0) {
        int n = i >> 9, k = i & 511;
        write2(g_wb1 + (size_t)n * 1024, 512, k, w1[n * 512 + k]);
    } else if (i < WC0 + WC1) {
        i -= WC0;
        int n = i >> 8, k = i & 255;
        write2(g_wb2 + (size_t)n * 512, 256, k, w2[n * 256 + k]);
    } else if (i < WC0 + WC1 + WC2) {
        i -= WC0 + WC1;
        int n = i / 448, k = i % 448;
        float v = (k < RDIM) ? w3[n * RDIM + k] : 0.0f;
        write2(g_wt0 + (size_t)n * 896, 448, k, v);
    } else {
        i -= WC0 + WC1 + WC2;
        int n = i >> 9, k = i & 511;
        write2(g_wt1 + (size_t)n * 1024, 512, k, w4[n * 512 + k]);
    }
}

// ---------------- bottom layer0: 13 -> 512, pair out -----------------------
#define B0_ROWS 32
__global__ void __launch_bounds__(256) bot0_kernel(
    const float* __restrict__ x,
    const float* __restrict__ w, const float* __restrict__ b)
{
    __shared__ float ws[512 * 13];
    __shared__ float bs[512];
    __shared__ float xs[B0_ROWS * 13];
    const int tid  = threadIdx.x;
    const int row0 = blockIdx.x * B0_ROWS;

    for (int i = tid; i < 512 * 13; i += 256) ws[i] = w[i];
    for (int i = tid; i < 512; i += 256)      bs[i] = b[i];
    for (int i = tid; i < B0_ROWS * 13; i += 256) xs[i] = x[row0 * 13 + i];
    __syncthreads();

    for (int o = tid; o < B0_ROWS * 512; o += 256) {
        int r = o >> 9, j = o & 511;
        float acc = bs[j];
        const float* xr = xs + r * 13;
        const float* wr = ws + j * 13;
#pragma unroll
        for (int k = 0; k < 13; k++) acc += xr[k] * wr[k];
        write2(g_h0 + (size_t)(row0 + r) * 1024, 512, j, fmaxf(acc, 0.0f));
    }
}

// ---------------- mma.sync bf16 GEMM, 3-stage cp.async, 3 CTAs/SM ----------
// A2/W2: [hi|lo] pairs, stride 2*Kp; logical [hi|lo|hi]x[hi|hi|lo] via chunk
// remap. BM in {128,64}, BN=64, BK=64. 256 threads: 4(M)x2(N) warps.
// mode 0: fp32 out Cf[ldc]; mode 1: [hi|lo] pair out C2 (Kp=KpOut).
#define NSTAGE 3
template<int BM>
__global__ void __launch_bounds__(256, 3) gemm_mma(
    const __nv_bfloat16* __restrict__ A2,
    const __nv_bfloat16* __restrict__ W2,
    const float* __restrict__ bias, int Kp,
    float* __restrict__ Cf, int ldc,
    __nv_bfloat16* __restrict__ C2, int KpOut, int mode)
{
    constexpr int MT     = BM / 64;          // m16 frags per warp
    constexpr int NBA    = BM / 32;          // A cp.async per thread
    constexpr int ABYTES = BM * 128;
    constexpr int STAGEB = ABYTES + 64 * 128;

    extern __shared__ char dynsm[];
    const int tid  = threadIdx.x;
    const int wid  = tid >> 5;
    const int lane = tid & 31;
    const int warp_m = wid & 3;
    const int warp_n = wid >> 2;
    const size_t row0 = (size_t)blockIdx.x * BM;
    const size_t col0 = (size_t)blockIdx.y * 64;

    uint32_t dbase = smem_u32(dynsm);
    uint32_t abase = (dbase + 1023) & ~1023u;

    const int lrow = tid >> 3;
    const int lcol = tid & 7;
    const int K2 = 2 * Kp;
    const int nz  = Kp / 64;
    const int nch = 3 * nz;
    const __nv_bfloat16* Abase = A2 + (row0 + lrow) * (size_t)K2 + lcol * 8;
    const __nv_bfloat16* Wbase = W2 + (col0 + lrow) * (size_t)K2 + lcol * 8;
    const uint32_t adst = sw128(lrow * 128 + lcol * 16);   // row-q adds 32*128

    // issue chunk t's loads into stage s
    auto issue = [&](int t, int s) {
        const int at = (t < 2 * nz) ? t : t - 2 * nz;      // A: [hi|lo|hi]
        const int wt = (t < nz)     ? t : t - nz;          // W: [hi|hi|lo]
        const uint32_t sb = abase + s * STAGEB;
        const __nv_bfloat16* Ab = Abase + at * 64;
        const __nv_bfloat16* Wb = Wbase + wt * 64;
#pragma unroll
        for (int q = 0; q < NBA; q++)
            CP_ASYNC16(sb + adst + q * 32 * 128, Ab + (size_t)q * 32 * K2);
#pragma unroll
        for (int q = 0; q < 2; q++)
            CP_ASYNC16(sb + ABYTES + adst + q * 32 * 128, Wb + (size_t)q * 32 * K2);
    };

    // ldmatrix lane offsets (relative to stage base)
    int abyte[MT], bbyte[2];
#pragma unroll
    for (int tm = 0; tm < MT; tm++)
        abyte[tm] = (warp_m * MT * 16 + tm * 16 + (lane & 15)) * 128 + (lane >> 4) * 16;
#pragma unroll
    for (int g = 0; g < 2; g++)
        bbyte[g] = (warp_n * 32 + g * 16 + (lane & 15)) * 128 + (lane >> 4) * 16;

    // accumulators (+bias)
    float c[MT][4][4];
    {
        const int cb = (int)col0 + warp_n * 32 + 2 * (lane & 3);
#pragma unroll
        for (int tn = 0; tn < 4; tn++) {
            float b0v = bias[cb + tn * 8];
            float b1v = bias[cb + tn * 8 + 1];
#pragma unroll
            for (int tm = 0; tm < MT; tm++) {
                c[tm][tn][0] = b0v; c[tm][tn][1] = b1v;
                c[tm][tn][2] = b0v; c[tm][tn][3] = b1v;
            }
        }
    }

    // prologue: stages 0,1 in flight
    issue(0, 0); CP_COMMIT();
    issue(1, 1); CP_COMMIT();

    for (int t = 0; t < nch; t++) {
        __syncthreads();                       // all warps done with stage (t+2)%3
        if (t + 2 < nch) { issue(t + 2, (t + 2) % NSTAGE); CP_COMMIT(); }
        const int rem = nch - 1 - t;
        if (rem >= 2)      CP_WAIT(2);
        else if (rem == 1) CP_WAIT(1);
        else               CP_WAIT(0);
        __syncthreads();                       // stage t visible to all warps

        const uint32_t sbase = abase + (t % NSTAGE) * STAGEB;
        const uint32_t bbase = sbase + ABYTES;
#pragma unroll
        for (int s = 0; s < 4; s++) {
            uint32_t af[MT][4];
#pragma unroll
            for (int tm = 0; tm < MT; tm++)
                LDSM_X4(af[tm][0], af[tm][1], af[tm][2], af[tm][3],
                        sbase + sw128(abyte[tm] + s * 32));
            // serialize B groups: lower register pressure for 3 CTAs/SM
#pragma unroll
            for (int g = 0; g < 2; g++) {
                uint32_t b0, b1, b2, b3;
                LDSM_X4(b0, b1, b2, b3, bbase + sw128(bbyte[g] + s * 32));
#pragma unroll
                for (int tm = 0; tm < MT; tm++) {
                    MMA16816(c[tm][g * 2 + 0],
                             af[tm][0], af[tm][1], af[tm][2], af[tm][3], b0, b2);
                    MMA16816(c[tm][g * 2 + 1],
                             af[tm][0], af[tm][1], af[tm][2], af[tm][3], b1, b3);
                }
            }
        }
    }

    // epilogue: fragments straight to global
#pragma unroll
    for (int tm = 0; tm < MT; tm++) {
        const size_t r = row0 + warp_m * MT * 16 + tm * 16 + (lane >> 2);
#pragma unroll
        for (int tn = 0; tn < 4; tn++) {
            const size_t cc = col0 + warp_n * 32 + tn * 8 + 2 * (lane & 3);
            float v0 = fmaxf(c[tm][tn][0], 0.0f);
            float v1 = fmaxf(c[tm][tn][1], 0.0f);
            float v2 = fmaxf(c[tm][tn][2], 0.0f);
            float v3 = fmaxf(c[tm][tn][3], 0.0f);
            if (mode == 0) {
                *(float2*)(Cf + r * ldc + cc)       = make_float2(v0, v1);
                *(float2*)(Cf + (r + 8) * ldc + cc) = make_float2(v2, v3);
            } else {
                store_pair2(C2 + r * (size_t)(2 * KpOut) + cc,       KpOut, v0, v1);
                store_pair2(C2 + (r + 8) * (size_t)(2 * KpOut) + cc, KpOut, v2, v3);
            }
        }
    }
}

// ---------------- embedding gather + interaction -> R pair -----------------
__global__ void __launch_bounds__(256) embed_kernel(
    const void*  __restrict__ lsi_raw,
    const float* __restrict__ emb)
{
    __shared__ __align__(16) float F[NF * FSTR];
    __shared__ int sidx[NT * LOOKUPS];

    const int b    = blockIdx.x;
    const int tid  = threadIdx.x;
    const int is64 = g_idx64;

    if (tid < NT * LOOKUPS) {
        int t = tid >> 2, l = tid & 3;
        long long off = (long long)t * (BATCH * LOOKUPS) + (long long)b * LOOKUPS + l;
        int idx = is64 ? (int)((const long long*)lsi_raw)[off]
                       : ((const int*)lsi_raw)[off];
        sidx[tid] = idx;
    }
    if (tid < EDIM)
        F[tid] = g_xbot[(size_t)b * EDIM + tid];
    __syncthreads();

    for (int q = tid; q < NT * 16; q += 256) {
        int t = q >> 4, v = q & 15;
        const float4* base = (const float4*)(emb + (size_t)t * TROWS * EDIM) + v;
        float4 acc = make_float4(0.f, 0.f, 0.f, 0.f);
#pragma unroll
        for (int l = 0; l < LOOKUPS; l++) {
            float4 e = base[(size_t)sidx[t * 4 + l] * 16];
            acc.x += e.x; acc.y += e.y; acc.z += e.z; acc.w += e.w;
        }
        acc.x *= 0.25f; acc.y *= 0.25f; acc.z *= 0.25f; acc.w *= 0.25f;
        *(float4*)(F + (t + 1) * FSTR + v * 4) = acc;
    }
    __syncthreads();

    __nv_bfloat16* Rrow = g_Rp + (size_t)b * 896;
    if (tid < EDIM) write2(Rrow, RKP, tid, F[tid]);
    for (int j = RDIM + tid; j < RKP; j += 256) write2(Rrow, RKP, j, 0.0f);

    for (int p = tid; p < NPAIR; p += 256) {
        int i = (int)((1.0f + sqrtf(1.0f + 8.0f * (float)p)) * 0.5f);
        while (i * (i - 1) / 2 > p) i--;
        while ((i + 1) * i / 2 <= p) i++;
        int j = p - i * (i - 1) / 2;
        const float* Fi = F + i * FSTR;
        const float* Fj = F + j * FSTR;
        float acc = 0.0f;
#pragma unroll 16
        for (int k = 0; k < EDIM; k++) acc += Fi[k] * Fj[k];
        write2(Rrow, RKP, 64 + p, acc);
    }
}

// ---------------- top layer2: 256 -> 1 (warp per row) ----------------------
__global__ void __launch_bounds__(256) top2_kernel(
    const float* __restrict__ A,
    const float* __restrict__ w, const float* __restrict__ b,
    float* __restrict__ out)
{
    const int warp = threadIdx.x >> 5, lane = threadIdx.x & 31;
    const int row  = blockIdx.x * 8 + warp;
    const float* a = A + (size_t)row * 256;
    float4 a0 = *(const float4*)(a + lane * 4);
    float4 a1 = *(const float4*)(a + 128 + lane * 4);
    float4 w0 = *(const float4*)(w + lane * 4);
    float4 w1 = *(const float4*)(w + 128 + lane * 4);
    float acc = a0.x * w0.x + a0.y * w0.y + a0.z * w0.z + a0.w * w0.w
              + a1.x * w1.x + a1.y * w1.y + a1.z * w1.z + a1.w * w1.w;
#pragma unroll
    for (int o = 16; o; o >>= 1) acc += __shfl_down_sync(0xffffffffu, acc, o);
    if (lane == 0) out[row] = acc + b[0];
}

// ---------------- launch ----------------
extern "C" void kernel_launch(void* const* d_in, const int* in_sizes, int n_in,
                              void* d_out, int out_size)
{
    const float* dense_x = (const float*)d_in[0];
    const void*  lsi     = d_in[2];
    const float* emb     = (const float*)d_in[3];
    const float* bw0 = (const float*)d_in[4];
    const float* bb0 = (const float*)d_in[5];
    const float* bw1 = (const float*)d_in[6];
    const float* bb1 = (const float*)d_in[7];
    const float* bw2 = (const float*)d_in[8];
    const float* bb2 = (const float*)d_in[9];
    const float* tw0 = (const float*)d_in[10];
    const float* tb0 = (const float*)d_in[11];
    const float* tw1 = (const float*)d_in[12];
    const float* tb1 = (const float*)d_in[13];
    const float* tw2 = (const float*)d_in[14];
    const float* tb2 = (const float*)d_in[15];
    float* out = (float*)d_out;

    __nv_bfloat16 *h0, *a1, *Rp, *t0, *wb1, *wb2, *wt0, *wt1;
    float *xbot, *t1;
    cudaGetSymbolAddress((void**)&h0,  g_h0);
    cudaGetSymbolAddress((void**)&a1,  g_a1);
    cudaGetSymbolAddress((void**)&Rp,  g_Rp);
    cudaGetSymbolAddress((void**)&t0,  g_t0);
    cudaGetSymbolAddress((void**)&wb1, g_wb1);
    cudaGetSymbolAddress((void**)&wb2, g_wb2);
    cudaGetSymbolAddress((void**)&wt0, g_wt0);
    cudaGetSymbolAddress((void**)&wt1, g_wt1);
    cudaGetSymbolAddress((void**)&xbot, g_xbot);
    cudaGetSymbolAddress((void**)&t1,   g_t1);

    const int dyn128 = 1024 + NSTAGE * (128 * 128 + 64 * 128);  // 74752
    const int dyn64  = 1024 + NSTAGE * (64 * 128 + 64 * 128);   // 50176
    cudaFuncSetAttribute(gemm_mma<128>, cudaFuncAttributeMaxDynamicSharedMemorySize, dyn128);
    cudaFuncSetAttribute(gemm_mma<64>,  cudaFuncAttributeMaxDynamicSharedMemorySize, dyn64);

    detect_kernel<<<1, 32>>>((const int*)lsi);
    wconv_all<<<(WCTOT + 255) / 256, 256>>>(bw1, bw2, tw0, tw1);

    // bottom MLP
    bot0_kernel<<<BATCH / B0_ROWS, 256>>>(dense_x, bw0, bb0);
    gemm_mma<128><<<dim3(BATCH / 128, 4), 256, dyn128>>>(h0, wb1, bb1, 512,
                                                         nullptr, 0, a1, 256, 1);
    gemm_mma<64><<<dim3(BATCH / 64, 1), 256, dyn64>>>(a1, wb2, bb2, 256,
                                                      xbot, 64, nullptr, 0, 0);
    // embeddings + interaction -> R pair
    embed_kernel<<<BATCH, 256>>>(lsi, emb);

    // top MLP
    gemm_mma<128><<<dim3(BATCH / 128, 8), 256, dyn128>>>(Rp, wt0, tb0, 448,
                                                         nullptr, 0, t0, 512, 1);
    gemm_mma<128><<<dim3(BATCH / 128, 4), 256, dyn128>>>(t0, wt1, tb1, 512,
                                                         t1, 256, nullptr, 0, 0);
    top2_kernel<<<BATCH / 8, 256>>>(t1, tw2, tb2, out);
}